// round 2
// baseline (speedup 1.0000x reference)
#include <cuda_runtime.h>
#include <math.h>

#define BATCH 8
#define CIN   64
#define HH    128
#define WW    128
#define COUT  64

// packed fp32x2 helpers (sm_100+)
#define FMA2(d, a, b, c) \
    asm("fma.rn.f32x2 %0, %1, %2, %3;" : "=l"(d) : "l"(a), "l"(b), "l"(c))
__device__ __forceinline__ unsigned long long pack2(float lo, float hi) {
    unsigned long long r;
    asm("mov.b64 %0, {%1, %2};" : "=l"(r) : "r"(__float_as_uint(lo)), "r"(__float_as_uint(hi)));
    return r;
}
__device__ __forceinline__ void unpack2(unsigned long long v, float& lo, float& hi) {
    unsigned int a, b;
    asm("mov.b64 {%0, %1}, %2;" : "=r"(a), "=r"(b) : "l"(v));
    lo = __uint_as_float(a); hi = __uint_as_float(b);
}

// Scratch (device globals; no allocations allowed)
__device__ __align__(16) float g_xnhwc[BATCH*HH*WW*CIN];   // 33.5 MB
__device__ __align__(16) float g_field[BATCH*HH*WW*27];    // 14.2 MB
__device__ __align__(16) float g_wr[9*CIN*COUT];           // w_dcn repacked [k][c][o]

// ---------------- transpose NCHW -> NHWC ----------------
__global__ void k_transpose(const float* __restrict__ x) {
    __shared__ float tile[32][33];
    int bh = blockIdx.z;
    int b = bh >> 7, h = bh & 127;
    int w0 = blockIdx.x * 32;
    int c0 = blockIdx.y * 32;
    int tx = threadIdx.x, ty = threadIdx.y;
    const float* src = x + ((b*CIN + c0)*HH + h)*WW + w0;
#pragma unroll
    for (int j = 0; j < 4; j++)
        tile[ty + 8*j][tx] = src[(ty + 8*j)*(HH*WW) + tx];
    __syncthreads();
    float* dst = g_xnhwc + ((b*HH + h)*WW + w0)*CIN + c0;
#pragma unroll
    for (int j = 0; j < 4; j++)
        dst[(ty + 8*j)*CIN + tx] = tile[tx][ty + 8*j];
}

// ---------------- repack w_dcn (o,c,ky,kx) -> [k][c][o] ----------------
__global__ void k_repack(const float* __restrict__ wdcn) {
    int i = blockIdx.x*256 + threadIdx.x;
    if (i >= 9*CIN*COUT) return;
    int o = i % COUT;
    int c = (i / COUT) % CIN;
    int k = i / (COUT*CIN);
    g_wr[i] = wdcn[(o*CIN + c)*9 + k];
}

// ---------------- offset conv: x (NCHW) -> field (B,H,W,27) ----------------
// tile 8 rows x 16 cols, 128 threads. out-pair packed f32x2 accumulators.
__global__ void __launch_bounds__(128) k_offconv(
        const float* __restrict__ x, const float* __restrict__ woff,
        const float* __restrict__ boff) {
    extern __shared__ float sm[];
    float* xs = sm;               // [64][180]  (10 rows * 18 cols)
    float* ws = sm + 64*180;      // [64][28]   current-k weight slice (o=27 zero)
    int b  = blockIdx.z;
    int h0 = blockIdx.y << 3;
    int w0 = blockIdx.x << 4;
    int tid = threadIdx.x;

    // fill haloed x tile (zero padding)
    for (int e = tid; e < 64*180; e += 128) {
        int c = e / 180;
        int rem = e - c*180;
        int r = rem / 18;
        int col = rem - r*18;
        int y = h0 - 1 + r, xw = w0 - 1 + col;
        float v = 0.f;
        if ((unsigned)y < HH && (unsigned)xw < WW)
            v = x[((b*CIN + c)*HH + y)*WW + xw];
        xs[e] = v;
    }

    int ty = tid >> 4, tx = tid & 15;
    unsigned long long acc2[14];      // outs (2j, 2j+1); slot 27 is pad
#pragma unroll
    for (int j = 0; j < 14; j++) acc2[j] = 0ull;

#pragma unroll 1
    for (int kk = 0; kk < 9; kk++) {
        __syncthreads();
        for (int e = tid; e < 64*28; e += 128) {
            int c = e / 28;
            int o = e - c*28;
            ws[e] = (o < 27) ? woff[(o*CIN + c)*9 + kk] : 0.f;
        }
        __syncthreads();
        int ky = kk/3, kx = kk - ky*3;
        int base = (ty + ky)*18 + tx + kx;
#pragma unroll 4
        for (int c = 0; c < 64; c++) {
            float xv = xs[c*180 + base];
            unsigned long long xv2 = pack2(xv, xv);
            const ulonglong2* w2 = (const ulonglong2*)(ws + c*28);
#pragma unroll
            for (int q = 0; q < 7; q++) {
                ulonglong2 wp = w2[q];
                FMA2(acc2[2*q],   xv2, wp.x, acc2[2*q]);
                FMA2(acc2[2*q+1], xv2, wp.y, acc2[2*q+1]);
            }
        }
    }

    int h = h0 + ty, w = w0 + tx;
    float* f = g_field + ((b*HH + h)*WW + w)*27;
    float outv[28];
#pragma unroll
    for (int j = 0; j < 14; j++) unpack2(acc2[j], outv[2*j], outv[2*j+1]);
#pragma unroll
    for (int o = 0; o < 27; o++) {
        float v = outv[o] + boff[o];
        if (o >= 18) v = 1.f/(1.f + __expf(-v));
        f[o] = v;
    }
}

// ---------------- fused bilinear sample + output GEMM ----------------
// block = one full image row (128 px) x 64 out, 256 threads.
// GEMM: warp w -> outs [8w, 8w+8); lane l -> pixels [4l, 4l+4). f32x2 packed.
__global__ void __launch_bounds__(256) k_main(float* __restrict__ out) {
    extern __shared__ float sm[];
    float* As = sm;               // [64][128]  32 KB  (channel-major)
    float* Bs = sm + 64*128;      // [64][64]   16 KB
    float* fs = sm + 64*128 + 64*64;  // [128][28] 14 KB
    int b = blockIdx.z, h = blockIdx.y;
    int tid = threadIdx.x;

    {   // cache per-pixel field values for this row
        const float* f = g_field + ((b*HH + h)*WW)*27;
        for (int e = tid; e < 128*27; e += 256) {
            int p = e / 27;
            int o = e - p*27;
            fs[p*28 + o] = f[e];
        }
    }

    unsigned long long acc2[2][8];   // [px-pair][out]
#pragma unroll
    for (int i = 0; i < 2; i++)
#pragma unroll
        for (int j = 0; j < 8; j++) acc2[i][j] = 0ull;

    int sp = tid >> 1, sq = tid & 1;   // sampling: pixel, channel-half
    int lane = tid & 31, wid = tid >> 5;  // gemm: px-group, out-group
    const float* xp = g_xnhwc + b*(HH*WW*CIN);

#pragma unroll 1
    for (int kk = 0; kk < 9; kk++) {
        __syncthreads();
        {   // load B tile for this k (same for all blocks -> L2-resident)
            const float4* s4 = (const float4*)(g_wr + kk*(CIN*COUT));
            float4* d4 = (float4*)Bs;
#pragma unroll
            for (int e = 0; e < 4; e++) d4[tid + 256*e] = s4[tid + 256*e];
        }
        {   // bilinear sample 32 channels of pixel sp
            int ky = kk/3, kx = kk - ky*3;
            float dy = fs[sp*28 + 2*kk];
            float dx = fs[sp*28 + 2*kk + 1];
            float m  = fs[sp*28 + 18 + kk];
            float py = dy + (float)(h - 1 + ky);
            float px = dx + (float)(sp - 1 + kx);
            float fy = floorf(py), fx = floorf(px);
            int y0 = (int)fy, x0 = (int)fx;
            float ay = py - fy, ax = px - fx;
            float w00 = (1.f-ay)*(1.f-ax)*m;
            float w01 = (1.f-ay)*ax*m;
            float w10 = ay*(1.f-ax)*m;
            float w11 = ay*ax*m;
            int y1 = y0 + 1, x1 = x0 + 1;
            if (!(((unsigned)y0 < HH) && ((unsigned)x0 < WW))) w00 = 0.f;
            if (!(((unsigned)y0 < HH) && ((unsigned)x1 < WW))) w01 = 0.f;
            if (!(((unsigned)y1 < HH) && ((unsigned)x0 < WW))) w10 = 0.f;
            if (!(((unsigned)y1 < HH) && ((unsigned)x1 < WW))) w11 = 0.f;
            int yc0 = min(max(y0, 0), HH-1);
            int yc1 = min(max(y1, 0), HH-1);
            int xc0 = min(max(x0, 0), WW-1);
            int xc1 = min(max(x1, 0), WW-1);
            const float4* t00 = (const float4*)(xp + (yc0*WW + xc0)*CIN) + sq*8;
            const float4* t01 = (const float4*)(xp + (yc0*WW + xc1)*CIN) + sq*8;
            const float4* t10 = (const float4*)(xp + (yc1*WW + xc0)*CIN) + sq*8;
            const float4* t11 = (const float4*)(xp + (yc1*WW + xc1)*CIN) + sq*8;
#pragma unroll
            for (int j = 0; j < 8; j++) {
                float4 a = t00[j], bq = t01[j], cq = t10[j], dq = t11[j];
                int c = sq*32 + j*4;
                As[(c+0)*128 + sp] = w00*a.x + w01*bq.x + w10*cq.x + w11*dq.x;
                As[(c+1)*128 + sp] = w00*a.y + w01*bq.y + w10*cq.y + w11*dq.y;
                As[(c+2)*128 + sp] = w00*a.z + w01*bq.z + w10*cq.z + w11*dq.z;
                As[(c+3)*128 + sp] = w00*a.w + w01*bq.w + w10*cq.w + w11*dq.w;
            }
        }
        __syncthreads();
        {   // 128x64x64 GEMM accumulate, f32x2 packed
            const float* Arow = As + lane*4;
            const float* Brow = Bs + wid*8;
#pragma unroll 4
            for (int c = 0; c < 64; c++) {
                ulonglong2 av = *(const ulonglong2*)(Arow + c*128);  // px pairs
                float4 b0 = *(const float4*)(Brow + c*64);
                float4 b1 = *(const float4*)(Brow + c*64 + 4);
                unsigned long long bd[8];
                bd[0] = pack2(b0.x, b0.x); bd[1] = pack2(b0.y, b0.y);
                bd[2] = pack2(b0.z, b0.z); bd[3] = pack2(b0.w, b0.w);
                bd[4] = pack2(b1.x, b1.x); bd[5] = pack2(b1.y, b1.y);
                bd[6] = pack2(b1.z, b1.z); bd[7] = pack2(b1.w, b1.w);
#pragma unroll
                for (int o = 0; o < 8; o++) {
                    FMA2(acc2[0][o], av.x, bd[o], acc2[0][o]);
                    FMA2(acc2[1][o], av.y, bd[o], acc2[1][o]);
                }
            }
        }
    }

    // write NCHW output: thread -> outs [8*wid, +8), px [4*lane, +4)
#pragma unroll
    for (int oo = 0; oo < 8; oo++) {
        int o = wid*8 + oo;
        float4 v;
        unpack2(acc2[0][oo], v.x, v.y);
        unpack2(acc2[1][oo], v.z, v.w);
        *(float4*)(out + ((b*COUT + o)*HH + h)*WW + lane*4) = v;
    }
}

extern "C" void kernel_launch(void* const* d_in, const int* in_sizes, int n_in,
                              void* d_out, int out_size) {
    const float* x    = (const float*)d_in[0];
    const float* woff = (const float*)d_in[1];
    const float* boff = (const float*)d_in[2];
    const float* wdcn = (const float*)d_in[3];
    float* out = (float*)d_out;

    k_transpose<<<dim3(WW/32, CIN/32, BATCH*HH), dim3(32, 8)>>>(x);
    k_repack<<<(9*CIN*COUT + 255)/256, 256>>>(wdcn);

    size_t smO = (size_t)(64*180 + 64*28) * sizeof(float);   // 53,248 B
    cudaFuncSetAttribute(k_offconv, cudaFuncAttributeMaxDynamicSharedMemorySize, (int)smO);
    k_offconv<<<dim3(WW/16, HH/8, BATCH), 128, smO>>>(x, woff, boff);

    size_t smM = (size_t)(64*128 + 64*64 + 128*28) * sizeof(float);  // 63,488 B
    cudaFuncSetAttribute(k_main, cudaFuncAttributeMaxDynamicSharedMemorySize, (int)smM);
    k_main<<<dim3(1, HH, BATCH), 256, smM>>>(out);
}

// round 4
// speedup vs baseline: 1.7692x; 1.7692x over previous
#include <cuda_runtime.h>
#include <cuda_bf16.h>
#include <math.h>
#include <stdint.h>

#define BATCH 8
#define CIN   64
#define HH    128
#define WW    128
#define COUT  64

// ---------- f32x2 helpers (offconv) ----------
#define FMA2(d, a, b, c) \
    asm("fma.rn.f32x2 %0, %1, %2, %3;" : "=l"(d) : "l"(a), "l"(b), "l"(c))
__device__ __forceinline__ unsigned long long pack2(float lo, float hi) {
    unsigned long long r;
    asm("mov.b64 %0, {%1, %2};" : "=l"(r) : "r"(__float_as_uint(lo)), "r"(__float_as_uint(hi)));
    return r;
}
__device__ __forceinline__ void unpack2(unsigned long long v, float& lo, float& hi) {
    unsigned int a, b;
    asm("mov.b64 {%0, %1}, %2;" : "=r"(a), "=r"(b) : "l"(v));
    lo = __uint_as_float(a); hi = __uint_as_float(b);
}

// ---------- mma helpers ----------
__device__ __forceinline__ uint32_t smem_u32(const void* p) {
    uint32_t a;
    asm("{ .reg .u64 t; cvta.to.shared.u64 t, %1; cvt.u32.u64 %0, t; }" : "=r"(a) : "l"(p));
    return a;
}
__device__ __forceinline__ void ldsm4(uint32_t* r, uint32_t addr) {
    asm volatile("ldmatrix.sync.aligned.m8n8.x4.shared.b16 {%0,%1,%2,%3}, [%4];"
        : "=r"(r[0]), "=r"(r[1]), "=r"(r[2]), "=r"(r[3]) : "r"(addr));
}
__device__ __forceinline__ void mma16816(float* c, const uint32_t* a, uint32_t b0, uint32_t b1) {
    asm volatile("mma.sync.aligned.m16n8k16.row.col.f32.bf16.bf16.f32 "
        "{%0,%1,%2,%3}, {%4,%5,%6,%7}, {%8,%9}, {%0,%1,%2,%3};"
        : "+f"(c[0]), "+f"(c[1]), "+f"(c[2]), "+f"(c[3])
        : "r"(a[0]), "r"(a[1]), "r"(a[2]), "r"(a[3]), "r"(b0), "r"(b1));
}
#define SWZ(o) ((o) ^ (((o) >> 3) & 0x70))

// ---------- scratch ----------
__device__ __align__(16) float g_xnhwc[BATCH*HH*WW*CIN];
__device__ __align__(16) float g_field[BATCH*HH*WW*27];
__device__ __align__(16) __nv_bfloat16 g_wbh[9*COUT*CIN];  // [k][o][c] hi
__device__ __align__(16) __nv_bfloat16 g_wbl[9*COUT*CIN];  // [k][o][c] lo

// ---------------- transpose NCHW -> NHWC ----------------
__global__ void k_transpose(const float* __restrict__ x) {
    __shared__ float tile[32][33];
    int bh = blockIdx.z;
    int b = bh >> 7, h = bh & 127;
    int w0 = blockIdx.x * 32;
    int c0 = blockIdx.y * 32;
    int tx = threadIdx.x, ty = threadIdx.y;
    const float* src = x + ((b*CIN + c0)*HH + h)*WW + w0;
#pragma unroll
    for (int j = 0; j < 4; j++)
        tile[ty + 8*j][tx] = src[(ty + 8*j)*(HH*WW) + tx];
    __syncthreads();
    float* dst = g_xnhwc + ((b*HH + h)*WW + w0)*CIN + c0;
#pragma unroll
    for (int j = 0; j < 4; j++)
        dst[(ty + 8*j)*CIN + tx] = tile[tx][ty + 8*j];
}

// ---------------- repack w_dcn -> [k][o][c] bf16 hi/lo ----------------
__global__ void k_repack(const float* __restrict__ wdcn) {
    int i = blockIdx.x*256 + threadIdx.x;
    if (i >= 9*COUT*CIN) return;
    int c = i & 63;
    int o = (i >> 6) & 63;
    int k = i >> 12;
    float v = wdcn[(o*CIN + c)*9 + k];
    __nv_bfloat16 hb = __float2bfloat16(v);
    g_wbh[i] = hb;
    g_wbl[i] = __float2bfloat16(v - __bfloat162float(hb));
}

// ---------------- offset conv (split channel halves) ----------------
__global__ void __launch_bounds__(128) k_offconv(
        const float* __restrict__ x, const float* __restrict__ woff,
        const float* __restrict__ boff) {
    extern __shared__ float smf[];
    float* xs = smf;            // [32][180]
    float* ws = smf + 32*180;   // [32][28]
    int b  = blockIdx.z;
    int h0 = blockIdx.y << 3;
    int w0 = blockIdx.x << 4;
    int tid = threadIdx.x;
    int ty = tid >> 4, tx = tid & 15;

    unsigned long long acc2[14];
#pragma unroll
    for (int j = 0; j < 14; j++) acc2[j] = 0ull;

#pragma unroll 1
    for (int ch = 0; ch < 2; ch++) {
        __syncthreads();
        for (int e = tid; e < 32*180; e += 128) {
            int c = e / 180;
            int rem = e - c*180;
            int r = rem / 18;
            int col = rem - r*18;
            int y = h0 - 1 + r, xw = w0 - 1 + col;
            float v = 0.f;
            if ((unsigned)y < HH && (unsigned)xw < WW)
                v = x[((b*CIN + ch*32 + c)*HH + y)*WW + xw];
            xs[e] = v;
        }
#pragma unroll 1
        for (int kk = 0; kk < 9; kk++) {
            __syncthreads();
            for (int e = tid; e < 32*28; e += 128) {
                int c = e / 28;
                int o = e - c*28;
                ws[e] = (o < 27) ? woff[(o*CIN + ch*32 + c)*9 + kk] : 0.f;
            }
            __syncthreads();
            int ky = kk/3, kx = kk - ky*3;
            int base = (ty + ky)*18 + tx + kx;
#pragma unroll 4
            for (int c = 0; c < 32; c++) {
                float xv = xs[c*180 + base];
                unsigned long long xv2 = pack2(xv, xv);
                const ulonglong2* w2 = (const ulonglong2*)(ws + c*28);
#pragma unroll
                for (int q = 0; q < 7; q++) {
                    ulonglong2 wp = w2[q];
                    FMA2(acc2[2*q],   xv2, wp.x, acc2[2*q]);
                    FMA2(acc2[2*q+1], xv2, wp.y, acc2[2*q+1]);
                }
            }
        }
    }

    int h = h0 + ty, w = w0 + tx;
    float* fptr = g_field + ((b*HH + h)*WW + w)*27;
    float outv[28];
#pragma unroll
    for (int j = 0; j < 14; j++) unpack2(acc2[j], outv[2*j], outv[2*j+1]);
#pragma unroll
    for (int o = 0; o < 27; o++) {
        float v = outv[o] + boff[o];
        if (o >= 18) v = 1.f/(1.f + __expf(-v));
        fptr[o] = v;
    }
}

// ---------------- fused bilinear sample + HMMA GEMM ----------------
// block = one image row (128 px), 256 threads = 8 warps.
// Warp w owns pixels [16w,16w+16): samples them into warp-local smem (bf16 hi/lo,
// SW128) and accumulates C[16px][64o] in register fragments across all 9 taps.
// 3-pass bf16 hi/lo error compensation: Ah*Bh + Ah*Bl + Al*Bh.
__global__ void __launch_bounds__(256) k_main(float* __restrict__ out) {
    extern __shared__ __align__(1024) char sm[];
    // layout: As (8 warps x 4KB: hi 2KB + lo 2KB) | Bs hi 8KB | Bs lo 8KB | fs 14KB
    const int BS_HI = 32768;
    const int BS_LO = 40960;
    const int FS    = 49152;
    float* fs = (float*)(sm + FS);
    uint32_t sbase = smem_u32(sm);

    int b = blockIdx.z, h = blockIdx.y;
    int tid = threadIdx.x, wid = tid >> 5, lane = tid & 31;

    {   // per-pixel field cache
        const float* f = g_field + ((b*HH + h)*WW)*27;
        for (int e = tid; e < 128*27; e += 256) {
            int p = e / 27;
            int o = e - p*27;
            fs[p*28 + o] = f[e];
        }
    }
    __syncthreads();

    float acc[8][4];
#pragma unroll
    for (int i = 0; i < 8; i++)
#pragma unroll
        for (int j = 0; j < 4; j++) acc[i][j] = 0.f;

    const float* xp = g_xnhwc + b*(HH*WW*CIN);
    int pxg = lane >> 3, chunk = lane & 7;
    uint32_t as_hi = sbase + wid*4096;
    uint32_t as_lo = as_hi + 2048;

#pragma unroll 1
    for (int kk = 0; kk < 9; kk++) {
        __syncthreads();   // Bs free (prev mma consumed)

        {   // stage B hi/lo swizzled (identical across blocks -> L2 hits)
            const float4* s4h = (const float4*)(g_wbh + kk*(COUT*CIN));
            const float4* s4l = (const float4*)(g_wbl + kk*(COUT*CIN));
#pragma unroll
            for (int r = 0; r < 2; r++) {
                int i = tid + r*256;
                uint32_t sw = SWZ((uint32_t)(i*16));
                *(float4*)(sm + BS_HI + sw) = s4h[i];
                *(float4*)(sm + BS_LO + sw) = s4l[i];
            }
        }

        int ky = kk/3, kx = kk - ky*3;
#pragma unroll 1
        for (int g = 0; g < 4; g++) {
            int pxl = g*4 + pxg;
            int px = wid*16 + pxl;
            const float* fp = fs + px*28;
            float dy = fp[2*kk], dx = fp[2*kk + 1], m = fp[18 + kk];
            float py  = dy + (float)(h - 1 + ky);
            float pxx = dx + (float)(px - 1 + kx);
            float fy = floorf(py), fx = floorf(pxx);
            int y0 = (int)fy, x0 = (int)fx;
            float ay = py - fy, ax = pxx - fx;
            float w00 = (1.f-ay)*(1.f-ax)*m;
            float w01 = (1.f-ay)*ax*m;
            float w10 = ay*(1.f-ax)*m;
            float w11 = ay*ax*m;
            int y1 = y0 + 1, x1 = x0 + 1;
            if (!(((unsigned)y0 < HH) && ((unsigned)x0 < WW))) w00 = 0.f;
            if (!(((unsigned)y0 < HH) && ((unsigned)x1 < WW))) w01 = 0.f;
            if (!(((unsigned)y1 < HH) && ((unsigned)x0 < WW))) w10 = 0.f;
            if (!(((unsigned)y1 < HH) && ((unsigned)x1 < WW))) w11 = 0.f;
            int yc0 = min(max(y0, 0), HH-1);
            int yc1 = min(max(y1, 0), HH-1);
            int xc0 = min(max(x0, 0), WW-1);
            int xc1 = min(max(x1, 0), WW-1);
            const float* b00 = xp + (yc0*WW + xc0)*CIN;
            const float* b01 = xp + (yc0*WW + xc1)*CIN;
            const float* b10 = xp + (yc1*WW + xc0)*CIN;
            const float* b11 = xp + (yc1*WW + xc1)*CIN;
#pragma unroll
            for (int half = 0; half < 2; half++) {
                int c0 = chunk*4 + half*32;
                float4 v00 = *(const float4*)(b00 + c0);
                float4 v01 = *(const float4*)(b01 + c0);
                float4 v10 = *(const float4*)(b10 + c0);
                float4 v11 = *(const float4*)(b11 + c0);
                float4 v;
                v.x = fmaf(w11, v11.x, fmaf(w10, v10.x, fmaf(w01, v01.x, w00*v00.x)));
                v.y = fmaf(w11, v11.y, fmaf(w10, v10.y, fmaf(w01, v01.y, w00*v00.y)));
                v.z = fmaf(w11, v11.z, fmaf(w10, v10.z, fmaf(w01, v01.z, w00*v00.z)));
                v.w = fmaf(w11, v11.w, fmaf(w10, v10.w, fmaf(w01, v01.w, w00*v00.w)));
                __nv_bfloat162 h01 = __float22bfloat162_rn(make_float2(v.x, v.y));
                __nv_bfloat162 h23 = __float22bfloat162_rn(make_float2(v.z, v.w));
                float2 hf01 = __bfloat1622float2(h01);
                float2 hf23 = __bfloat1622float2(h23);
                __nv_bfloat162 l01 = __float22bfloat162_rn(make_float2(v.x - hf01.x, v.y - hf01.y));
                __nv_bfloat162 l23 = __float22bfloat162_rn(make_float2(v.z - hf23.x, v.w - hf23.y));
                uint32_t off = SWZ((uint32_t)(pxl*128 + c0*2));
                *(uint2*)(sm + wid*4096 + off)        = make_uint2(*(uint32_t*)&h01, *(uint32_t*)&h23);
                *(uint2*)(sm + wid*4096 + 2048 + off) = make_uint2(*(uint32_t*)&l01, *(uint32_t*)&l23);
            }
        }

        __syncthreads();   // Bs staged + own-warp A visible

        // ldmatrix + mma
        uint32_t a_row = (uint32_t)(lane & 15) * 128;
        uint32_t b_row = (uint32_t)((lane & 7) + ((lane >> 4) << 3)) * 128;
#pragma unroll
        for (int ks = 0; ks < 4; ks++) {
            uint32_t ah[4], al[4];
            uint32_t a_off = SWZ(a_row + (uint32_t)(ks*16 + (lane>>4)*8)*2);
            ldsm4(ah, as_hi + a_off);
            ldsm4(al, as_lo + a_off);
            uint32_t kc = (uint32_t)(ks*16 + ((lane>>3)&1)*8)*2;
#pragma unroll
            for (int ntp = 0; ntp < 4; ntp++) {
                uint32_t bh[4], bl[4];
                uint32_t b_off = SWZ((uint32_t)(ntp*16)*128 + b_row + kc);
                ldsm4(bh, sbase + BS_HI + b_off);
                ldsm4(bl, sbase + BS_LO + b_off);
                mma16816(acc[ntp*2],   ah, bh[0], bh[1]);
                mma16816(acc[ntp*2+1], ah, bh[2], bh[3]);
                mma16816(acc[ntp*2],   ah, bl[0], bl[1]);
                mma16816(acc[ntp*2+1], ah, bl[2], bl[3]);
                mma16816(acc[ntp*2],   al, bh[0], bh[1]);
                mma16816(acc[ntp*2+1], al, bh[2], bh[3]);
            }
        }
    }

    // epilogue: direct stores (8 lanes/o give 32B segments)
    int r = lane >> 2, cq = (lane & 3)*2;
    int px0 = wid*16 + r;
#pragma unroll
    for (int nt = 0; nt < 8; nt++) {
        int o0 = nt*8 + cq;
        float* o_ptr0 = out + ((b*COUT + o0)*HH + h)*WW;
        float* o_ptr1 = out + ((b*COUT + o0 + 1)*HH + h)*WW;
        o_ptr0[px0]     = acc[nt][0];
        o_ptr1[px0]     = acc[nt][1];
        o_ptr0[px0 + 8] = acc[nt][2];
        o_ptr1[px0 + 8] = acc[nt][3];
    }
}

extern "C" void kernel_launch(void* const* d_in, const int* in_sizes, int n_in,
                              void* d_out, int out_size) {
    const float* x    = (const float*)d_in[0];
    const float* woff = (const float*)d_in[1];
    const float* boff = (const float*)d_in[2];
    const float* wdcn = (const float*)d_in[3];
    float* out = (float*)d_out;

    k_transpose<<<dim3(WW/32, CIN/32, BATCH*HH), dim3(32, 8)>>>(x);
    k_repack<<<(9*COUT*CIN + 255)/256, 256>>>(wdcn);

    size_t smO = (size_t)(32*180 + 32*28) * sizeof(float);   // 26,624 B
    cudaFuncSetAttribute(k_offconv, cudaFuncAttributeMaxDynamicSharedMemorySize, (int)smO);
    k_offconv<<<dim3(WW/16, HH/8, BATCH), 128, smO>>>(x, woff, boff);

    size_t smM = 49152 + 128*28*4;   // 63,488 B
    cudaFuncSetAttribute(k_main, cudaFuncAttributeMaxDynamicSharedMemorySize, (int)smM);
    k_main<<<dim3(1, HH, BATCH), 256, smM>>>(out);
}

// round 5
// speedup vs baseline: 2.6159x; 1.4786x over previous
#include <cuda_runtime.h>
#include <cuda_bf16.h>
#include <math.h>
#include <stdint.h>

#define BATCH 8
#define CIN   64
#define HH    128
#define WW    128
#define COUT  64

// ---------- mma helpers ----------
__device__ __forceinline__ uint32_t smem_u32(const void* p) {
    uint32_t a;
    asm("{ .reg .u64 t; cvta.to.shared.u64 t, %1; cvt.u32.u64 %0, t; }" : "=r"(a) : "l"(p));
    return a;
}
__device__ __forceinline__ void ldsm4(uint32_t* r, uint32_t addr) {
    asm volatile("ldmatrix.sync.aligned.m8n8.x4.shared.b16 {%0,%1,%2,%3}, [%4];"
        : "=r"(r[0]), "=r"(r[1]), "=r"(r[2]), "=r"(r[3]) : "r"(addr));
}
__device__ __forceinline__ void mma16816(float* c, const uint32_t* a, uint32_t b0, uint32_t b1) {
    asm volatile("mma.sync.aligned.m16n8k16.row.col.f32.bf16.bf16.f32 "
        "{%0,%1,%2,%3}, {%4,%5,%6,%7}, {%8,%9}, {%0,%1,%2,%3};"
        : "+f"(c[0]), "+f"(c[1]), "+f"(c[2]), "+f"(c[3])
        : "r"(a[0]), "r"(a[1]), "r"(a[2]), "r"(a[3]), "r"(b0), "r"(b1));
}
#define SWZ(o) ((o) ^ (((o) >> 3) & 0x70))

// ---------- scratch ----------
__device__ __align__(16) float g_xnhwc[BATCH*HH*WW*CIN];
__device__ __align__(16) float g_field[BATCH*HH*WW*27];
__device__ __align__(16) __nv_bfloat16 g_xbh[BATCH*HH*WW*CIN];   // NHWC bf16 hi
__device__ __align__(16) __nv_bfloat16 g_xbl[BATCH*HH*WW*CIN];   // NHWC bf16 lo
__device__ __align__(16) __nv_bfloat16 g_wbh[9*COUT*CIN];        // dcn [k][o][c] hi
__device__ __align__(16) __nv_bfloat16 g_wbl[9*COUT*CIN];        // dcn [k][o][c] lo
__device__ __align__(16) __nv_bfloat16 g_obh[9*32*CIN];          // off [k][o(pad32)][c] hi
__device__ __align__(16) __nv_bfloat16 g_obl[9*32*CIN];          // off [k][o(pad32)][c] lo

// ---------------- transpose NCHW -> NHWC (+ bf16 hi/lo copies) ----------------
__global__ void k_transpose(const float* __restrict__ x) {
    __shared__ float tile[32][33];
    int bh = blockIdx.z;
    int b = bh >> 7, h = bh & 127;
    int w0 = blockIdx.x * 32;
    int c0 = blockIdx.y * 32;
    int tx = threadIdx.x, ty = threadIdx.y;
    const float* src = x + ((b*CIN + c0)*HH + h)*WW + w0;
#pragma unroll
    for (int j = 0; j < 4; j++)
        tile[ty + 8*j][tx] = src[(ty + 8*j)*(HH*WW) + tx];
    __syncthreads();
    size_t base = (size_t)((b*HH + h)*WW + w0)*CIN + c0;
#pragma unroll
    for (int j = 0; j < 4; j++) {
        float v = tile[tx][ty + 8*j];
        size_t idx = base + (size_t)(ty + 8*j)*CIN + tx;
        g_xnhwc[idx] = v;
        __nv_bfloat16 hb = __float2bfloat16(v);
        g_xbh[idx] = hb;
        g_xbl[idx] = __float2bfloat16(v - __bfloat162float(hb));
    }
}

// ---------------- repack weights -> bf16 hi/lo ----------------
__global__ void k_repack(const float* __restrict__ wdcn, const float* __restrict__ woff) {
    int i = blockIdx.x*256 + threadIdx.x;
    if (i < 9*COUT*CIN) {
        int c = i & 63;
        int o = (i >> 6) & 63;
        int k = i >> 12;
        float v = wdcn[(o*CIN + c)*9 + k];
        __nv_bfloat16 hb = __float2bfloat16(v);
        g_wbh[i] = hb;
        g_wbl[i] = __float2bfloat16(v - __bfloat162float(hb));
    }
    int j = i - 9*COUT*CIN;
    if (j >= 0 && j < 9*32*CIN) {
        int c = j & 63;
        int o = (j >> 6) & 31;
        int k = j >> 11;
        float v = (o < 27) ? woff[(o*CIN + c)*9 + k] : 0.f;
        __nv_bfloat16 hb = __float2bfloat16(v);
        g_obh[j] = hb;
        g_obl[j] = __float2bfloat16(v - __bfloat162float(hb));
    }
}

// ---------------- offset conv via HMMA implicit GEMM ----------------
// block = one image row (128 px), 256 threads / 8 warps; warp w owns px [16w,16w+16).
// Per tap: shifted-window copy of x (bf16 hi/lo) -> SW128 smem; 3-pass bf16 mma;
// N=32 (27 real outs). Epilogue: bias (+sigmoid on mask ch) -> g_field.
__global__ void __launch_bounds__(256) k_offconv2(const float* __restrict__ boff) {
    extern __shared__ __align__(1024) char sm[];
    const int AS_HI = 0;        // 16 KB
    const int AS_LO = 16384;    // 16 KB
    const int BS_HI = 32768;    // 4 KB
    const int BS_LO = 36864;    // 4 KB
    uint32_t sbase = smem_u32(sm);

    int b = blockIdx.z, h = blockIdx.y;
    int tid = threadIdx.x, wid = tid >> 5, lane = tid & 31;

    float acc[4][4];
#pragma unroll
    for (int i = 0; i < 4; i++)
#pragma unroll
        for (int j = 0; j < 4; j++) acc[i][j] = 0.f;

    uint32_t as_hi = sbase + AS_HI + wid*2048;
    uint32_t as_lo = sbase + AS_LO + wid*2048;
    uint32_t a_row = (uint32_t)(lane & 15) * 128;
    uint32_t b_row = (uint32_t)((lane & 7) + ((lane >> 4) << 3)) * 128;

#pragma unroll 1
    for (int kk = 0; kk < 9; kk++) {
        int ky = kk/3, kx = kk - ky*3;
        int y = h + ky - 1;
        if ((unsigned)y >= HH) continue;        // block-uniform: zero-padded row
        __syncthreads();                         // prev tap's mma done

        {   // stage B hi/lo (32x64 bf16 = 4KB each)
            const float4* s4h = (const float4*)(g_obh + kk*(32*CIN));
            const float4* s4l = (const float4*)(g_obl + kk*(32*CIN));
            uint32_t sw = SWZ((uint32_t)(tid*16));
            *(float4*)(sm + BS_HI + sw) = s4h[tid];
            *(float4*)(sm + BS_LO + sw) = s4l[tid];
        }
        {   // stage shifted A window (128px x 64c bf16 hi/lo)
            const __nv_bfloat16* rowh = g_xbh + (size_t)((b*HH + y)*WW)*CIN;
            const __nv_bfloat16* rowl = g_xbl + (size_t)((b*HH + y)*WW)*CIN;
#pragma unroll
            for (int r = 0; r < 4; r++) {
                int i = tid + r*256;
                int px = i >> 3, c16 = i & 7;
                int s = px + kx - 1;
                uint4 vh = make_uint4(0,0,0,0), vl = make_uint4(0,0,0,0);
                if ((unsigned)s < WW) {
                    vh = *(const uint4*)(rowh + s*CIN + c16*8);
                    vl = *(const uint4*)(rowl + s*CIN + c16*8);
                }
                uint32_t off = SWZ((uint32_t)(px*128 + c16*16));
                *(uint4*)(sm + AS_HI + off) = vh;
                *(uint4*)(sm + AS_LO + off) = vl;
            }
        }
        __syncthreads();

#pragma unroll
        for (int ks = 0; ks < 4; ks++) {
            uint32_t ah[4], al[4];
            uint32_t a_off = SWZ(a_row + (uint32_t)(ks*16 + (lane>>4)*8)*2);
            ldsm4(ah, as_hi + a_off);
            ldsm4(al, as_lo + a_off);
            uint32_t kc = (uint32_t)(ks*16 + ((lane>>3)&1)*8)*2;
#pragma unroll
            for (int ntp = 0; ntp < 2; ntp++) {
                uint32_t bh[4], bl[4];
                uint32_t b_off = SWZ((uint32_t)(ntp*16)*128 + b_row + kc);
                ldsm4(bh, sbase + BS_HI + b_off);
                ldsm4(bl, sbase + BS_LO + b_off);
                mma16816(acc[ntp*2],   ah, bh[0], bh[1]);
                mma16816(acc[ntp*2+1], ah, bh[2], bh[3]);
                mma16816(acc[ntp*2],   ah, bl[0], bl[1]);
                mma16816(acc[ntp*2+1], ah, bl[2], bl[3]);
                mma16816(acc[ntp*2],   al, bh[0], bh[1]);
                mma16816(acc[ntp*2+1], al, bh[2], bh[3]);
            }
        }
    }

    // epilogue: bias + sigmoid(mask), write g_field [pix][27]
    int r = lane >> 2, cq = (lane & 3)*2;
    int px0 = wid*16 + r;
    float* frow = g_field + (size_t)((b*HH + h)*WW)*27;
#pragma unroll
    for (int nt = 0; nt < 4; nt++) {
#pragma unroll
        for (int oi = 0; oi < 2; oi++) {
            int o = nt*8 + cq + oi;
            if (o < 27) {
                float bias = boff[o];
                float v0 = acc[nt][oi]     + bias;
                float v1 = acc[nt][2 + oi] + bias;
                if (o >= 18) {
                    v0 = 1.f/(1.f + __expf(-v0));
                    v1 = 1.f/(1.f + __expf(-v1));
                }
                frow[(size_t)px0*27 + o]       = v0;
                frow[(size_t)(px0 + 8)*27 + o] = v1;
            }
        }
    }
}

// ---------------- fused bilinear sample + HMMA GEMM (unchanged from R4) ----------------
__global__ void __launch_bounds__(256) k_main(float* __restrict__ out) {
    extern __shared__ __align__(1024) char sm[];
    const int BS_HI = 32768;
    const int BS_LO = 40960;
    const int FS    = 49152;
    float* fs = (float*)(sm + FS);
    uint32_t sbase = smem_u32(sm);

    int b = blockIdx.z, h = blockIdx.y;
    int tid = threadIdx.x, wid = tid >> 5, lane = tid & 31;

    {   // per-pixel field cache
        const float* f = g_field + ((b*HH + h)*WW)*27;
        for (int e = tid; e < 128*27; e += 256) {
            int p = e / 27;
            int o = e - p*27;
            fs[p*28 + o] = f[e];
        }
    }
    __syncthreads();

    float acc[8][4];
#pragma unroll
    for (int i = 0; i < 8; i++)
#pragma unroll
        for (int j = 0; j < 4; j++) acc[i][j] = 0.f;

    const float* xp = g_xnhwc + b*(HH*WW*CIN);
    int pxg = lane >> 3, chunk = lane & 7;
    uint32_t as_hi = sbase + wid*4096;
    uint32_t as_lo = as_hi + 2048;

#pragma unroll 1
    for (int kk = 0; kk < 9; kk++) {
        __syncthreads();

        {   // stage B hi/lo swizzled
            const float4* s4h = (const float4*)(g_wbh + kk*(COUT*CIN));
            const float4* s4l = (const float4*)(g_wbl + kk*(COUT*CIN));
#pragma unroll
            for (int r = 0; r < 2; r++) {
                int i = tid + r*256;
                uint32_t sw = SWZ((uint32_t)(i*16));
                *(float4*)(sm + BS_HI + sw) = s4h[i];
                *(float4*)(sm + BS_LO + sw) = s4l[i];
            }
        }

        int ky = kk/3, kx = kk - ky*3;
#pragma unroll 1
        for (int g = 0; g < 4; g++) {
            int pxl = g*4 + pxg;
            int px = wid*16 + pxl;
            const float* fp = fs + px*28;
            float dy = fp[2*kk], dx = fp[2*kk + 1], m = fp[18 + kk];
            float py  = dy + (float)(h - 1 + ky);
            float pxx = dx + (float)(px - 1 + kx);
            float fy = floorf(py), fx = floorf(pxx);
            int y0 = (int)fy, x0 = (int)fx;
            float ay = py - fy, ax = pxx - fx;
            float w00 = (1.f-ay)*(1.f-ax)*m;
            float w01 = (1.f-ay)*ax*m;
            float w10 = ay*(1.f-ax)*m;
            float w11 = ay*ax*m;
            int y1 = y0 + 1, x1 = x0 + 1;
            if (!(((unsigned)y0 < HH) && ((unsigned)x0 < WW))) w00 = 0.f;
            if (!(((unsigned)y0 < HH) && ((unsigned)x1 < WW))) w01 = 0.f;
            if (!(((unsigned)y1 < HH) && ((unsigned)x0 < WW))) w10 = 0.f;
            if (!(((unsigned)y1 < HH) && ((unsigned)x1 < WW))) w11 = 0.f;
            int yc0 = min(max(y0, 0), HH-1);
            int yc1 = min(max(y1, 0), HH-1);
            int xc0 = min(max(x0, 0), WW-1);
            int xc1 = min(max(x1, 0), WW-1);
            const float* b00 = xp + (yc0*WW + xc0)*CIN;
            const float* b01 = xp + (yc0*WW + xc1)*CIN;
            const float* b10 = xp + (yc1*WW + xc0)*CIN;
            const float* b11 = xp + (yc1*WW + xc1)*CIN;
#pragma unroll
            for (int half = 0; half < 2; half++) {
                int c0 = chunk*4 + half*32;
                float4 v00 = *(const float4*)(b00 + c0);
                float4 v01 = *(const float4*)(b01 + c0);
                float4 v10 = *(const float4*)(b10 + c0);
                float4 v11 = *(const float4*)(b11 + c0);
                float4 v;
                v.x = fmaf(w11, v11.x, fmaf(w10, v10.x, fmaf(w01, v01.x, w00*v00.x)));
                v.y = fmaf(w11, v11.y, fmaf(w10, v10.y, fmaf(w01, v01.y, w00*v00.y)));
                v.z = fmaf(w11, v11.z, fmaf(w10, v10.z, fmaf(w01, v01.z, w00*v00.z)));
                v.w = fmaf(w11, v11.w, fmaf(w10, v10.w, fmaf(w01, v01.w, w00*v00.w)));
                __nv_bfloat162 h01 = __float22bfloat162_rn(make_float2(v.x, v.y));
                __nv_bfloat162 h23 = __float22bfloat162_rn(make_float2(v.z, v.w));
                float2 hf01 = __bfloat1622float2(h01);
                float2 hf23 = __bfloat1622float2(h23);
                __nv_bfloat162 l01 = __float22bfloat162_rn(make_float2(v.x - hf01.x, v.y - hf01.y));
                __nv_bfloat162 l23 = __float22bfloat162_rn(make_float2(v.z - hf23.x, v.w - hf23.y));
                uint32_t off = SWZ((uint32_t)(pxl*128 + c0*2));
                *(uint2*)(sm + wid*4096 + off)        = make_uint2(*(uint32_t*)&h01, *(uint32_t*)&h23);
                *(uint2*)(sm + wid*4096 + 2048 + off) = make_uint2(*(uint32_t*)&l01, *(uint32_t*)&l23);
            }
        }

        __syncthreads();

        uint32_t a_row = (uint32_t)(lane & 15) * 128;
        uint32_t b_row = (uint32_t)((lane & 7) + ((lane >> 4) << 3)) * 128;
#pragma unroll
        for (int ks = 0; ks < 4; ks++) {
            uint32_t ah[4], al[4];
            uint32_t a_off = SWZ(a_row + (uint32_t)(ks*16 + (lane>>4)*8)*2);
            ldsm4(ah, as_hi + a_off);
            ldsm4(al, as_lo + a_off);
            uint32_t kc = (uint32_t)(ks*16 + ((lane>>3)&1)*8)*2;
#pragma unroll
            for (int ntp = 0; ntp < 4; ntp++) {
                uint32_t bh[4], bl[4];
                uint32_t b_off = SWZ((uint32_t)(ntp*16)*128 + b_row + kc);
                ldsm4(bh, sbase + BS_HI + b_off);
                ldsm4(bl, sbase + BS_LO + b_off);
                mma16816(acc[ntp*2],   ah, bh[0], bh[1]);
                mma16816(acc[ntp*2+1], ah, bh[2], bh[3]);
                mma16816(acc[ntp*2],   ah, bl[0], bl[1]);
                mma16816(acc[ntp*2+1], ah, bl[2], bl[3]);
                mma16816(acc[ntp*2],   al, bh[0], bh[1]);
                mma16816(acc[ntp*2+1], al, bh[2], bh[3]);
            }
        }
    }

    int r = lane >> 2, cq = (lane & 3)*2;
    int px0 = wid*16 + r;
#pragma unroll
    for (int nt = 0; nt < 8; nt++) {
        int o0 = nt*8 + cq;
        float* o_ptr0 = out + ((b*COUT + o0)*HH + h)*WW;
        float* o_ptr1 = out + ((b*COUT + o0 + 1)*HH + h)*WW;
        o_ptr0[px0]     = acc[nt][0];
        o_ptr1[px0]     = acc[nt][1];
        o_ptr0[px0 + 8] = acc[nt][2];
        o_ptr1[px0 + 8] = acc[nt][3];
    }
}

extern "C" void kernel_launch(void* const* d_in, const int* in_sizes, int n_in,
                              void* d_out, int out_size) {
    const float* x    = (const float*)d_in[0];
    const float* woff = (const float*)d_in[1];
    const float* boff = (const float*)d_in[2];
    const float* wdcn = (const float*)d_in[3];
    float* out = (float*)d_out;

    k_transpose<<<dim3(WW/32, CIN/32, BATCH*HH), dim3(32, 8)>>>(x);
    int repack_n = 9*COUT*CIN + 9*32*CIN;
    k_repack<<<(repack_n + 255)/256, 256>>>(wdcn, woff);

    size_t smO = 40960;   // As 32K + Bs 8K
    cudaFuncSetAttribute(k_offconv2, cudaFuncAttributeMaxDynamicSharedMemorySize, (int)smO);
    k_offconv2<<<dim3(1, HH, BATCH), 256, smO>>>(boff);

    size_t smM = 49152 + 128*28*4;   // 63,488 B
    cudaFuncSetAttribute(k_main, cudaFuncAttributeMaxDynamicSharedMemorySize, (int)smM);
    k_main<<<dim3(1, HH, BATCH), 256, smM>>>(out);
}

// round 6
// speedup vs baseline: 2.7208x; 1.0401x over previous
#include <cuda_runtime.h>
#include <cuda_bf16.h>
#include <math.h>
#include <stdint.h>

#define BATCH 8
#define CIN   64
#define HH    128
#define WW    128
#define COUT  64

// ---------- mma helpers ----------
__device__ __forceinline__ uint32_t smem_u32(const void* p) {
    uint32_t a;
    asm("{ .reg .u64 t; cvta.to.shared.u64 t, %1; cvt.u32.u64 %0, t; }" : "=r"(a) : "l"(p));
    return a;
}
__device__ __forceinline__ void ldsm4(uint32_t* r, uint32_t addr) {
    asm volatile("ldmatrix.sync.aligned.m8n8.x4.shared.b16 {%0,%1,%2,%3}, [%4];"
        : "=r"(r[0]), "=r"(r[1]), "=r"(r[2]), "=r"(r[3]) : "r"(addr));
}
__device__ __forceinline__ void mma16816(float* c, const uint32_t* a, uint32_t b0, uint32_t b1) {
    asm volatile("mma.sync.aligned.m16n8k16.row.col.f32.bf16.bf16.f32 "
        "{%0,%1,%2,%3}, {%4,%5,%6,%7}, {%8,%9}, {%0,%1,%2,%3};"
        : "+f"(c[0]), "+f"(c[1]), "+f"(c[2]), "+f"(c[3])
        : "r"(a[0]), "r"(a[1]), "r"(a[2]), "r"(a[3]), "r"(b0), "r"(b1));
}
__device__ __forceinline__ void mbar_wait(uint32_t addr, uint32_t parity) {
    asm volatile(
        "{\n\t.reg .pred P;\n"
        "WL_%=:\n\t"
        "mbarrier.try_wait.parity.acquire.cta.shared::cta.b64 P, [%0], %1, 0x989680;\n\t"
        "@P bra WD_%=;\n\t"
        "bra WL_%=;\n"
        "WD_%=:\n\t}"
        :: "r"(addr), "r"(parity) : "memory");
}
#define MBAR_ARRIVE(a) asm volatile("mbarrier.arrive.shared.b64 _, [%0];" :: "r"(a) : "memory")
#define SWZ(o) ((o) ^ (((o) >> 3) & 0x70))
#define CP16(dst, src) \
    asm volatile("cp.async.ca.shared.global [%0], [%1], 16;" :: "r"(dst), "l"(src))
#define CP16Z(dst, src, sz) \
    asm volatile("cp.async.ca.shared.global [%0], [%1], 16, %2;" :: "r"(dst), "l"(src), "r"(sz))

// ---------- scratch ----------
__device__ __align__(16) float g_xnhwc[BATCH*HH*WW*CIN];
__device__ __align__(16) float g_field[BATCH*HH*WW*27];
__device__ __align__(16) __nv_bfloat16 g_xbh[BATCH*HH*WW*CIN];   // NHWC bf16 hi
__device__ __align__(16) __nv_bfloat16 g_xbl[BATCH*HH*WW*CIN];   // NHWC bf16 lo
__device__ __align__(16) __nv_bfloat16 g_wbh[9*COUT*CIN];        // dcn [k][o][c] hi
__device__ __align__(16) __nv_bfloat16 g_wbl[9*COUT*CIN];        // dcn [k][o][c] lo
__device__ __align__(16) __nv_bfloat16 g_obh[9*32*CIN];          // off [k][o(pad32)][c] hi
__device__ __align__(16) __nv_bfloat16 g_obl[9*32*CIN];          // off [k][o(pad32)][c] lo

// ---------------- transpose NCHW -> NHWC (+ bf16 hi/lo copies) ----------------
__global__ void k_transpose(const float* __restrict__ x) {
    __shared__ float tile[32][33];
    int bh = blockIdx.z;
    int b = bh >> 7, h = bh & 127;
    int w0 = blockIdx.x * 32;
    int c0 = blockIdx.y * 32;
    int tx = threadIdx.x, ty = threadIdx.y;
    const float* src = x + ((b*CIN + c0)*HH + h)*WW + w0;
#pragma unroll
    for (int j = 0; j < 4; j++)
        tile[ty + 8*j][tx] = src[(ty + 8*j)*(HH*WW) + tx];
    __syncthreads();
    size_t base = (size_t)((b*HH + h)*WW + w0)*CIN + c0;
#pragma unroll
    for (int j = 0; j < 4; j++) {
        float v = tile[tx][ty + 8*j];
        size_t idx = base + (size_t)(ty + 8*j)*CIN + tx;
        g_xnhwc[idx] = v;
        __nv_bfloat16 hb = __float2bfloat16(v);
        g_xbh[idx] = hb;
        g_xbl[idx] = __float2bfloat16(v - __bfloat162float(hb));
    }
}

// ---------------- repack weights -> bf16 hi/lo ----------------
__global__ void k_repack(const float* __restrict__ wdcn, const float* __restrict__ woff) {
    int i = blockIdx.x*256 + threadIdx.x;
    if (i < 9*COUT*CIN) {
        int c = i & 63;
        int o = (i >> 6) & 63;
        int k = i >> 12;
        float v = wdcn[(o*CIN + c)*9 + k];
        __nv_bfloat16 hb = __float2bfloat16(v);
        g_wbh[i] = hb;
        g_wbl[i] = __float2bfloat16(v - __bfloat162float(hb));
    }
    int j = i - 9*COUT*CIN;
    if (j >= 0 && j < 9*32*CIN) {
        int c = j & 63;
        int o = (j >> 6) & 31;
        int k = j >> 11;
        float v = (o < 27) ? woff[(o*CIN + c)*9 + k] : 0.f;
        __nv_bfloat16 hb = __float2bfloat16(v);
        g_obh[j] = hb;
        g_obl[j] = __float2bfloat16(v - __bfloat162float(hb));
    }
}

// ---------------- offset conv: cp.async double-buffered HMMA ----------------
// smem: A[2] @ 0/32768 (hi 16K + lo 16K each); B[2] @ 65536/73728 (hi 4K + lo 4K)
__device__ __forceinline__ void off_stage(uint32_t sbase, int b, int h, int kk,
                                          int buf, int tid) {
    int ky = kk/3, kx = kk - ky*3;
    int y = h + ky - 1;
    bool yok = (unsigned)y < HH;
    int yc = min(max(y, 0), HH-1);
    {   // B: 256 hi chunks + 256 lo chunks, one each per thread
        const float4* s4h = (const float4*)(g_obh + kk*(32*CIN));
        const float4* s4l = (const float4*)(g_obl + kk*(32*CIN));
        uint32_t d = sbase + 65536 + buf*8192 + SWZ((uint32_t)(tid*16));
        CP16(d,        s4h + tid);
        CP16(d + 4096, s4l + tid);
    }
    const __nv_bfloat16* rowh = g_xbh + ((size_t)(b*HH + yc)*WW)*CIN;
    const __nv_bfloat16* rowl = g_xbl + ((size_t)(b*HH + yc)*WW)*CIN;
#pragma unroll
    for (int r = 0; r < 4; r++) {
        int i = tid + r*256;
        int px = i >> 3, c16 = i & 7;
        int s = px + kx - 1;
        int sz = (yok && (unsigned)s < WW) ? 16 : 0;
        int sc = min(max(s, 0), WW-1);
        uint32_t d = sbase + buf*32768 + SWZ((uint32_t)(px*128 + c16*16));
        CP16Z(d,         rowh + sc*CIN + c16*8, sz);
        CP16Z(d + 16384, rowl + sc*CIN + c16*8, sz);
    }
}

__global__ void __launch_bounds__(256) k_offconv2(const float* __restrict__ boff) {
    extern __shared__ __align__(1024) char sm[];
    uint32_t sbase = smem_u32(sm);
    int b = blockIdx.z, h = blockIdx.y;
    int tid = threadIdx.x, wid = tid >> 5, lane = tid & 31;

    float acc[4][4];
#pragma unroll
    for (int i = 0; i < 4; i++)
#pragma unroll
        for (int j = 0; j < 4; j++) acc[i][j] = 0.f;

    uint32_t a_row = (uint32_t)(lane & 15) * 128;
    uint32_t b_row = (uint32_t)((lane & 7) + ((lane >> 4) << 3)) * 128;

    off_stage(sbase, b, h, 0, 0, tid);
    asm volatile("cp.async.commit_group;" ::: "memory");

#pragma unroll 1
    for (int kk = 0; kk < 9; kk++) {
        if (kk < 8) {   // prefetch next tap (prev mma on that buffer done: end-of-iter sync)
            off_stage(sbase, b, h, kk + 1, (kk + 1) & 1, tid);
            asm volatile("cp.async.commit_group;" ::: "memory");
            asm volatile("cp.async.wait_group 1;" ::: "memory");
        } else {
            asm volatile("cp.async.wait_group 0;" ::: "memory");
        }
        __syncthreads();

        uint32_t asb = sbase + (kk & 1)*32768 + wid*2048;
        uint32_t bsb = sbase + 65536 + (kk & 1)*8192;
#pragma unroll
        for (int ks = 0; ks < 4; ks++) {
            uint32_t ah[4], al[4];
            uint32_t a_off = SWZ(a_row + (uint32_t)(ks*16 + (lane>>4)*8)*2);
            ldsm4(ah, asb + a_off);
            ldsm4(al, asb + 16384 + a_off);
            uint32_t kc = (uint32_t)(ks*16 + ((lane>>3)&1)*8)*2;
#pragma unroll
            for (int ntp = 0; ntp < 2; ntp++) {
                uint32_t bh[4], bl[4];
                uint32_t b_off = SWZ((uint32_t)(ntp*16)*128 + b_row + kc);
                ldsm4(bh, bsb + b_off);
                ldsm4(bl, bsb + 4096 + b_off);
                mma16816(acc[ntp*2],   ah, bh[0], bh[1]);
                mma16816(acc[ntp*2+1], ah, bh[2], bh[3]);
                mma16816(acc[ntp*2],   ah, bl[0], bl[1]);
                mma16816(acc[ntp*2+1], ah, bl[2], bl[3]);
                mma16816(acc[ntp*2],   al, bh[0], bh[1]);
                mma16816(acc[ntp*2+1], al, bh[2], bh[3]);
            }
        }
        __syncthreads();   // all reads of this buffer done before it is re-staged
    }

    // epilogue: bias + sigmoid(mask), write g_field [pix][27]
    int r = lane >> 2, cq = (lane & 3)*2;
    int px0 = wid*16 + r;
    float* frow = g_field + (size_t)((b*HH + h)*WW)*27;
#pragma unroll
    for (int nt = 0; nt < 4; nt++) {
#pragma unroll
        for (int oi = 0; oi < 2; oi++) {
            int o = nt*8 + cq + oi;
            if (o < 27) {
                float bias = boff[o];
                float v0 = acc[nt][oi]     + bias;
                float v1 = acc[nt][2 + oi] + bias;
                if (o >= 18) {
                    v0 = 1.f/(1.f + __expf(-v0));
                    v1 = 1.f/(1.f + __expf(-v1));
                }
                frow[(size_t)px0*27 + o]       = v0;
                frow[(size_t)(px0 + 8)*27 + o] = v1;
            }
        }
    }
}

// ---------------- k_main: warp-specialized sample + HMMA ----------------
// 384 threads: warps 0-7 producers (sample 16 px each), warps 8-11 consumers
// (mma, 32px x 64o each). Double-buffered As (2x32K) + Bs (2x16K), mbarriers.
// smem: As[2] @ 0/32768 (warp chunk wid*4096: hi +0, lo +2048)
//       Bs[2] @ 65536/81920 (hi +0 8K, lo +8192)
//       fs @ 98304 (14336), mbar @ 112640 (full0,full1,emp0,emp1)
__global__ void __launch_bounds__(384) k_main(float* __restrict__ out) {
    extern __shared__ __align__(1024) char sm[];
    const int BS0 = 65536, FS0 = 98304, MB = 112640;
    float* fs = (float*)(sm + FS0);
    uint32_t sbase = smem_u32(sm);
    uint32_t mb_full = sbase + MB;        // +0, +8
    uint32_t mb_emp  = sbase + MB + 16;   // +0, +8

    int b = blockIdx.z, h = blockIdx.y;
    int tid = threadIdx.x, wid = tid >> 5, lane = tid & 31;

    if (tid == 0) {
        asm volatile("mbarrier.init.shared.b64 [%0], %1;" :: "r"(mb_full),     "r"(256u) : "memory");
        asm volatile("mbarrier.init.shared.b64 [%0], %1;" :: "r"(mb_full + 8), "r"(256u) : "memory");
        asm volatile("mbarrier.init.shared.b64 [%0], %1;" :: "r"(mb_emp),      "r"(128u) : "memory");
        asm volatile("mbarrier.init.shared.b64 [%0], %1;" :: "r"(mb_emp + 8),  "r"(128u) : "memory");
    }
    {   // per-pixel field cache (all 384 threads)
        const float* f = g_field + ((size_t)(b*HH + h)*WW)*27;
        for (int e = tid; e < 128*27; e += 384) {
            int p = e / 27;
            int o = e - p*27;
            fs[p*28 + o] = f[e];
        }
    }
    __syncthreads();

    if (wid < 8) {
        // ================= producers =================
        const float* xp = g_xnhwc + (size_t)b*(HH*WW*CIN);
        int pxg = lane >> 3, chunk = lane & 7;
#pragma unroll 1
        for (int kk = 0; kk < 9; kk++) {
            int buf = kk & 1, u = kk >> 1;
            if (kk >= 2) mbar_wait(mb_emp + buf*8, (u - 1) & 1);

            {   // stage B hi/lo for this tap (L2-resident across blocks)
                const float4* s4h = (const float4*)(g_wbh + kk*(COUT*CIN));
                const float4* s4l = (const float4*)(g_wbl + kk*(COUT*CIN));
                char* bsb = sm + BS0 + buf*16384;
#pragma unroll
                for (int r = 0; r < 2; r++) {
                    int i = tid + r*256;
                    uint32_t sw = SWZ((uint32_t)(i*16));
                    *(float4*)(bsb + sw)        = s4h[i];
                    *(float4*)(bsb + 8192 + sw) = s4l[i];
                }
            }
            char* asb = sm + buf*32768 + wid*4096;
            int ky = kk/3, kx = kk - ky*3;
#pragma unroll 1
            for (int g = 0; g < 4; g++) {
                int pxl = g*4 + pxg;
                int px = wid*16 + pxl;
                const float* fp = fs + px*28;
                float dy = fp[2*kk], dx = fp[2*kk + 1], m = fp[18 + kk];
                float py  = dy + (float)(h - 1 + ky);
                float pxx = dx + (float)(px - 1 + kx);
                float fy = floorf(py), fx = floorf(pxx);
                int y0 = (int)fy, x0 = (int)fx;
                float ay = py - fy, ax = pxx - fx;
                float w00 = (1.f-ay)*(1.f-ax)*m;
                float w01 = (1.f-ay)*ax*m;
                float w10 = ay*(1.f-ax)*m;
                float w11 = ay*ax*m;
                int y1 = y0 + 1, x1 = x0 + 1;
                if (!(((unsigned)y0 < HH) && ((unsigned)x0 < WW))) w00 = 0.f;
                if (!(((unsigned)y0 < HH) && ((unsigned)x1 < WW))) w01 = 0.f;
                if (!(((unsigned)y1 < HH) && ((unsigned)x0 < WW))) w10 = 0.f;
                if (!(((unsigned)y1 < HH) && ((unsigned)x1 < WW))) w11 = 0.f;
                int yc0 = min(max(y0, 0), HH-1);
                int yc1 = min(max(y1, 0), HH-1);
                int xc0 = min(max(x0, 0), WW-1);
                int xc1 = min(max(x1, 0), WW-1);
                const float* b00 = xp + (yc0*WW + xc0)*CIN;
                const float* b01 = xp + (yc0*WW + xc1)*CIN;
                const float* b10 = xp + (yc1*WW + xc0)*CIN;
                const float* b11 = xp + (yc1*WW + xc1)*CIN;
#pragma unroll
                for (int half = 0; half < 2; half++) {
                    int c0 = chunk*4 + half*32;
                    float4 v00 = *(const float4*)(b00 + c0);
                    float4 v01 = *(const float4*)(b01 + c0);
                    float4 v10 = *(const float4*)(b10 + c0);
                    float4 v11 = *(const float4*)(b11 + c0);
                    float4 v;
                    v.x = fmaf(w11, v11.x, fmaf(w10, v10.x, fmaf(w01, v01.x, w00*v00.x)));
                    v.y = fmaf(w11, v11.y, fmaf(w10, v10.y, fmaf(w01, v01.y, w00*v00.y)));
                    v.z = fmaf(w11, v11.z, fmaf(w10, v10.z, fmaf(w01, v01.z, w00*v00.z)));
                    v.w = fmaf(w11, v11.w, fmaf(w10, v10.w, fmaf(w01, v01.w, w00*v00.w)));
                    __nv_bfloat162 h01 = __float22bfloat162_rn(make_float2(v.x, v.y));
                    __nv_bfloat162 h23 = __float22bfloat162_rn(make_float2(v.z, v.w));
                    float2 hf01 = __bfloat1622float2(h01);
                    float2 hf23 = __bfloat1622float2(h23);
                    __nv_bfloat162 l01 = __float22bfloat162_rn(make_float2(v.x - hf01.x, v.y - hf01.y));
                    __nv_bfloat162 l23 = __float22bfloat162_rn(make_float2(v.z - hf23.x, v.w - hf23.y));
                    uint32_t off = SWZ((uint32_t)(pxl*128 + c0*2));
                    *(uint2*)(asb + off)        = make_uint2(*(uint32_t*)&h01, *(uint32_t*)&h23);
                    *(uint2*)(asb + 2048 + off) = make_uint2(*(uint32_t*)&l01, *(uint32_t*)&l23);
                }
            }
            MBAR_ARRIVE(mb_full + buf*8);
        }
    } else {
        // ================= consumers =================
        int cw = wid - 8;
        float acc[2][8][4];
#pragma unroll
        for (int m = 0; m < 2; m++)
#pragma unroll
            for (int j = 0; j < 8; j++)
#pragma unroll
                for (int q = 0; q < 4; q++) acc[m][j][q] = 0.f;

        uint32_t a_row = (uint32_t)(lane & 15) * 128;
        uint32_t b_row = (uint32_t)((lane & 7) + ((lane >> 4) << 3)) * 128;

#pragma unroll 1
        for (int kk = 0; kk < 9; kk++) {
            int buf = kk & 1, u = kk >> 1;
            mbar_wait(mb_full + buf*8, u & 1);
            uint32_t asb = sbase + buf*32768;
            uint32_t bsb = sbase + BS0 + buf*16384;
#pragma unroll
            for (int ks = 0; ks < 4; ks++) {
                uint32_t ah[2][4], al[2][4];
                uint32_t a_off = SWZ(a_row + (uint32_t)(ks*16 + (lane>>4)*8)*2);
#pragma unroll
                for (int m = 0; m < 2; m++) {
                    uint32_t base = asb + (uint32_t)(2*cw + m)*4096;
                    ldsm4(ah[m], base + a_off);
                    ldsm4(al[m], base + 2048 + a_off);
                }
                uint32_t kc = (uint32_t)(ks*16 + ((lane>>3)&1)*8)*2;
#pragma unroll
                for (int nt = 0; nt < 4; nt++) {
                    uint32_t bh[4], bl[4];
                    uint32_t b_off = SWZ((uint32_t)(nt*16)*128 + b_row + kc);
                    ldsm4(bh, bsb + b_off);
                    ldsm4(bl, bsb + 8192 + b_off);
#pragma unroll
                    for (int m = 0; m < 2; m++) {
                        mma16816(acc[m][2*nt],   ah[m], bh[0], bh[1]);
                        mma16816(acc[m][2*nt+1], ah[m], bh[2], bh[3]);
                        mma16816(acc[m][2*nt],   ah[m], bl[0], bl[1]);
                        mma16816(acc[m][2*nt+1], ah[m], bl[2], bl[3]);
                        mma16816(acc[m][2*nt],   al[m], bh[0], bh[1]);
                        mma16816(acc[m][2*nt+1], al[m], bh[2], bh[3]);
                    }
                }
            }
            MBAR_ARRIVE(mb_emp + buf*8);
        }

        // epilogue
        int r = lane >> 2, cq = (lane & 3)*2;
#pragma unroll
        for (int m = 0; m < 2; m++) {
            int px0 = cw*32 + m*16 + r;
#pragma unroll
            for (int j = 0; j < 8; j++) {
                int o0 = j*8 + cq;
                float* p0 = out + ((size_t)(b*COUT + o0)*HH + h)*WW;
                float* p1 = out + ((size_t)(b*COUT + o0 + 1)*HH + h)*WW;
                p0[px0]     = acc[m][j][0];
                p1[px0]     = acc[m][j][1];
                p0[px0 + 8] = acc[m][j][2];
                p1[px0 + 8] = acc[m][j][3];
            }
        }
    }
}

extern "C" void kernel_launch(void* const* d_in, const int* in_sizes, int n_in,
                              void* d_out, int out_size) {
    const float* x    = (const float*)d_in[0];
    const float* woff = (const float*)d_in[1];
    const float* boff = (const float*)d_in[2];
    const float* wdcn = (const float*)d_in[3];
    float* out = (float*)d_out;

    k_transpose<<<dim3(WW/32, CIN/32, BATCH*HH), dim3(32, 8)>>>(x);
    int repack_n = 9*COUT*CIN + 9*32*CIN;
    k_repack<<<(repack_n + 255)/256, 256>>>(wdcn, woff);

    size_t smO = 81920;   // A[2] 64K + B[2] 16K
    cudaFuncSetAttribute(k_offconv2, cudaFuncAttributeMaxDynamicSharedMemorySize, (int)smO);
    k_offconv2<<<dim3(1, HH, BATCH), 256, smO>>>(boff);

    size_t smM = 112704;  // As[2] 64K + Bs[2] 32K + fs 14K + mbar
    cudaFuncSetAttribute(k_main, cudaFuncAttributeMaxDynamicSharedMemorySize, (int)smM);
    k_main<<<dim3(1, HH, BATCH), 384, smM>>>(out);
}

// round 9
// speedup vs baseline: 2.7539x; 1.0122x over previous
#include <cuda_runtime.h>
#include <cuda_bf16.h>
#include <math.h>
#include <stdint.h>

#define BATCH 8
#define CIN   64
#define HH    128
#define WW    128
#define COUT  64

// ---------- packed f32x2 helpers ----------
#define FMA2(d, a, b, c) \
    asm("fma.rn.f32x2 %0, %1, %2, %3;" : "=l"(d) : "l"(a), "l"(b), "l"(c))
#define MUL2(d, a, b) \
    asm("mul.rn.f32x2 %0, %1, %2;" : "=l"(d) : "l"(a), "l"(b))
// cvt.rn.bf16x2.f32 d, a, b  => d = {hi=a(bf16), lo=b(bf16)}
#define CVTBF2(r, hi, lo) \
    asm("cvt.rn.bf16x2.f32 %0, %1, %2;" : "=r"(r) : "f"(hi), "f"(lo))
__device__ __forceinline__ unsigned long long pack2f(float lo, float hi) {
    unsigned long long r;
    asm("mov.b64 %0, {%1, %2};" : "=l"(r) : "r"(__float_as_uint(lo)), "r"(__float_as_uint(hi)));
    return r;
}
__device__ __forceinline__ void unpack2f(unsigned long long v, float& lo, float& hi) {
    unsigned int a, b;
    asm("mov.b64 {%0, %1}, %2;" : "=r"(a), "=r"(b) : "l"(v));
    lo = __uint_as_float(a); hi = __uint_as_float(b);
}

// ---------- mma helpers ----------
__device__ __forceinline__ uint32_t smem_u32(const void* p) {
    uint32_t a;
    asm("{ .reg .u64 t; cvta.to.shared.u64 t, %1; cvt.u32.u64 %0, t; }" : "=r"(a) : "l"(p));
    return a;
}
__device__ __forceinline__ void ldsm4(uint32_t* r, uint32_t addr) {
    asm volatile("ldmatrix.sync.aligned.m8n8.x4.shared.b16 {%0,%1,%2,%3}, [%4];"
        : "=r"(r[0]), "=r"(r[1]), "=r"(r[2]), "=r"(r[3]) : "r"(addr));
}
__device__ __forceinline__ void mma16816(float* c, const uint32_t* a, uint32_t b0, uint32_t b1) {
    asm volatile("mma.sync.aligned.m16n8k16.row.col.f32.bf16.bf16.f32 "
        "{%0,%1,%2,%3}, {%4,%5,%6,%7}, {%8,%9}, {%0,%1,%2,%3};"
        : "+f"(c[0]), "+f"(c[1]), "+f"(c[2]), "+f"(c[3])
        : "r"(a[0]), "r"(a[1]), "r"(a[2]), "r"(a[3]), "r"(b0), "r"(b1));
}
#define SWZ(o) ((o) ^ (((o) >> 3) & 0x70))
#define CP16(dst, src) \
    asm volatile("cp.async.ca.shared.global [%0], [%1], 16;" :: "r"(dst), "l"(src))
#define CP16Z(dst, src, sz) \
    asm volatile("cp.async.ca.shared.global [%0], [%1], 16, %2;" :: "r"(dst), "l"(src), "r"(sz))

// ---------- scratch ----------
__device__ __align__(16) float g_xnhwc[BATCH*HH*WW*CIN];
__device__ __align__(16) float g_field[BATCH*HH*WW*27];
__device__ __align__(16) __nv_bfloat16 g_xbh[BATCH*HH*WW*CIN];   // NHWC bf16 hi
__device__ __align__(16) __nv_bfloat16 g_xbl[BATCH*HH*WW*CIN];   // NHWC bf16 lo
__device__ __align__(16) __nv_bfloat16 g_wbh[9*COUT*CIN];        // dcn [k][o][c] hi
__device__ __align__(16) __nv_bfloat16 g_wbl[9*COUT*CIN];        // dcn [k][o][c] lo
__device__ __align__(16) __nv_bfloat16 g_obh[9*32*CIN];          // off [k][o(pad32)][c] hi
__device__ __align__(16) __nv_bfloat16 g_obl[9*32*CIN];          // off [k][o(pad32)][c] lo

// ---------------- transpose NCHW -> NHWC (+ bf16 hi/lo copies) ----------------
__global__ void k_transpose(const float* __restrict__ x) {
    __shared__ float tile[32][33];
    int bh = blockIdx.z;
    int b = bh >> 7, h = bh & 127;
    int w0 = blockIdx.x * 32;
    int c0 = blockIdx.y * 32;
    int tx = threadIdx.x, ty = threadIdx.y;
    const float* src = x + ((b*CIN + c0)*HH + h)*WW + w0;
#pragma unroll
    for (int j = 0; j < 4; j++)
        tile[ty + 8*j][tx] = src[(ty + 8*j)*(HH*WW) + tx];
    __syncthreads();
    size_t base = (size_t)((b*HH + h)*WW + w0)*CIN + c0;
#pragma unroll
    for (int j = 0; j < 4; j++) {
        float v = tile[tx][ty + 8*j];
        size_t idx = base + (size_t)(ty + 8*j)*CIN + tx;
        g_xnhwc[idx] = v;
        __nv_bfloat16 hb = __float2bfloat16(v);
        g_xbh[idx] = hb;
        g_xbl[idx] = __float2bfloat16(v - __bfloat162float(hb));
    }
}

// ---------------- repack weights -> bf16 hi/lo ----------------
__global__ void k_repack(const float* __restrict__ wdcn, const float* __restrict__ woff) {
    int i = blockIdx.x*256 + threadIdx.x;
    if (i < 9*COUT*CIN) {
        int c = i & 63;
        int o = (i >> 6) & 63;
        int k = i >> 12;
        float v = wdcn[(o*CIN + c)*9 + k];
        __nv_bfloat16 hb = __float2bfloat16(v);
        g_wbh[i] = hb;
        g_wbl[i] = __float2bfloat16(v - __bfloat162float(hb));
    }
    int j = i - 9*COUT*CIN;
    if (j >= 0 && j < 9*32*CIN) {
        int c = j & 63;
        int o = (j >> 6) & 31;
        int k = j >> 11;
        float v = (o < 27) ? woff[(o*CIN + c)*9 + k] : 0.f;
        __nv_bfloat16 hb = __float2bfloat16(v);
        g_obh[j] = hb;
        g_obl[j] = __float2bfloat16(v - __bfloat162float(hb));
    }
}

// ---------------- offset conv: cp.async double-buffered HMMA (R6, unchanged) ----------------
__device__ __forceinline__ void off_stage(uint32_t sbase, int b, int h, int kk,
                                          int buf, int tid) {
    int ky = kk/3, kx = kk - ky*3;
    int y = h + ky - 1;
    bool yok = (unsigned)y < HH;
    int yc = min(max(y, 0), HH-1);
    {
        const float4* s4h = (const float4*)(g_obh + kk*(32*CIN));
        const float4* s4l = (const float4*)(g_obl + kk*(32*CIN));
        uint32_t d = sbase + 65536 + buf*8192 + SWZ((uint32_t)(tid*16));
        CP16(d,        s4h + tid);
        CP16(d + 4096, s4l + tid);
    }
    const __nv_bfloat16* rowh = g_xbh + ((size_t)(b*HH + yc)*WW)*CIN;
    const __nv_bfloat16* rowl = g_xbl + ((size_t)(b*HH + yc)*WW)*CIN;
#pragma unroll
    for (int r = 0; r < 4; r++) {
        int i = tid + r*256;
        int px = i >> 3, c16 = i & 7;
        int s = px + kx - 1;
        int sz = (yok && (unsigned)s < WW) ? 16 : 0;
        int sc = min(max(s, 0), WW-1);
        uint32_t d = sbase + buf*32768 + SWZ((uint32_t)(px*128 + c16*16));
        CP16Z(d,         rowh + sc*CIN + c16*8, sz);
        CP16Z(d + 16384, rowl + sc*CIN + c16*8, sz);
    }
}

__global__ void __launch_bounds__(256) k_offconv2(const float* __restrict__ boff) {
    extern __shared__ __align__(1024) char sm[];
    uint32_t sbase = smem_u32(sm);
    int b = blockIdx.z, h = blockIdx.y;
    int tid = threadIdx.x, wid = tid >> 5, lane = tid & 31;

    float acc[4][4];
#pragma unroll
    for (int i = 0; i < 4; i++)
#pragma unroll
        for (int j = 0; j < 4; j++) acc[i][j] = 0.f;

    uint32_t a_row = (uint32_t)(lane & 15) * 128;
    uint32_t b_row = (uint32_t)((lane & 7) + ((lane >> 4) << 3)) * 128;

    off_stage(sbase, b, h, 0, 0, tid);
    asm volatile("cp.async.commit_group;" ::: "memory");

#pragma unroll 1
    for (int kk = 0; kk < 9; kk++) {
        if (kk < 8) {
            off_stage(sbase, b, h, kk + 1, (kk + 1) & 1, tid);
            asm volatile("cp.async.commit_group;" ::: "memory");
            asm volatile("cp.async.wait_group 1;" ::: "memory");
        } else {
            asm volatile("cp.async.wait_group 0;" ::: "memory");
        }
        __syncthreads();

        uint32_t asb = sbase + (kk & 1)*32768 + wid*2048;
        uint32_t bsb = sbase + 65536 + (kk & 1)*8192;
#pragma unroll
        for (int ks = 0; ks < 4; ks++) {
            uint32_t ah[4], al[4];
            uint32_t a_off = SWZ(a_row + (uint32_t)(ks*16 + (lane>>4)*8)*2);
            ldsm4(ah, asb + a_off);
            ldsm4(al, asb + 16384 + a_off);
            uint32_t kc = (uint32_t)(ks*16 + ((lane>>3)&1)*8)*2;
#pragma unroll
            for (int ntp = 0; ntp < 2; ntp++) {
                uint32_t bh[4], bl[4];
                uint32_t b_off = SWZ((uint32_t)(ntp*16)*128 + b_row + kc);
                ldsm4(bh, bsb + b_off);
                ldsm4(bl, bsb + 4096 + b_off);
                mma16816(acc[ntp*2],   ah, bh[0], bh[1]);
                mma16816(acc[ntp*2+1], ah, bh[2], bh[3]);
                mma16816(acc[ntp*2],   ah, bl[0], bl[1]);
                mma16816(acc[ntp*2+1], ah, bl[2], bl[3]);
                mma16816(acc[ntp*2],   al, bh[0], bh[1]);
                mma16816(acc[ntp*2+1], al, bh[2], bh[3]);
            }
        }
        __syncthreads();
    }

    int r = lane >> 2, cq = (lane & 3)*2;
    int px0 = wid*16 + r;
    float* frow = g_field + (size_t)((b*HH + h)*WW)*27;
#pragma unroll
    for (int nt = 0; nt < 4; nt++) {
#pragma unroll
        for (int oi = 0; oi < 2; oi++) {
            int o = nt*8 + cq + oi;
            if (o < 27) {
                float bias = boff[o];
                float v0 = acc[nt][oi]     + bias;
                float v1 = acc[nt][2 + oi] + bias;
                if (o >= 18) {
                    v0 = 1.f/(1.f + __expf(-v0));
                    v1 = 1.f/(1.f + __expf(-v1));
                }
                frow[(size_t)px0*27 + o]       = v0;
                frow[(size_t)(px0 + 8)*27 + o] = v1;
            }
        }
    }
}

// ---------------- k_main: homogeneous, 32px x 32o warp tiles, f32x2 sampling,
//                  cp.async double-buffered B ----------------
// smem: As hi @0 (16K), As lo @16384 (16K); Bs[2] @32768 stride 16384 (hi +0, lo +8192);
//       fs @65536 (14336). Total 79872.
__global__ void __launch_bounds__(256, 2) k_main(float* __restrict__ out) {
    extern __shared__ __align__(1024) char sm[];
    const int AS_HI = 0, AS_LO = 16384, BS0 = 32768, FS0 = 65536;
    float* fs = (float*)(sm + FS0);
    uint32_t sbase = smem_u32(sm);

    int b = blockIdx.z, h = blockIdx.y;
    int tid = threadIdx.x, wid = tid >> 5, lane = tid & 31;

    {   // per-pixel field cache
        const float* f = g_field + ((size_t)(b*HH + h)*WW)*27;
        for (int e = tid; e < 128*27; e += 256) {
            int p = e / 27;
            int o = e - p*27;
            fs[p*28 + o] = f[e];
        }
    }

    // prologue: stage B for tap 0 into buf 0
    {
        const char* sh = (const char*)(g_wbh);
        const char* sl = (const char*)(g_wbl);
#pragma unroll
        for (int r = 0; r < 2; r++) {
            int i = tid + r*256;
            uint32_t sw = SWZ((uint32_t)(i*16));
            CP16(sbase + BS0 + sw,        sh + i*16);
            CP16(sbase + BS0 + 8192 + sw, sl + i*16);
        }
        asm volatile("cp.async.commit_group;" ::: "memory");
    }
    __syncthreads();   // fs visible to all warps before any sampling read

    float acc[2][4][4];
#pragma unroll
    for (int m = 0; m < 2; m++)
#pragma unroll
        for (int j = 0; j < 4; j++)
#pragma unroll
            for (int q = 0; q < 4; q++) acc[m][j][q] = 0.f;

    const float* xp = g_xnhwc + (size_t)b*(HH*WW*CIN);
    int pxg = lane >> 3, chunk = lane & 7;
    int pxbase = (wid & 3)*32, obase = (wid >> 2)*32;

#pragma unroll 1
    for (int kk = 0; kk < 9; kk++) {
        int buf = kk & 1;
        if (kk < 8) {   // prefetch next tap's B into other buffer
            const char* sh = (const char*)(g_wbh + (kk+1)*(COUT*CIN));
            const char* sl = (const char*)(g_wbl + (kk+1)*(COUT*CIN));
            uint32_t bb = sbase + BS0 + (buf^1)*16384;
#pragma unroll
            for (int r = 0; r < 2; r++) {
                int i = tid + r*256;
                uint32_t sw = SWZ((uint32_t)(i*16));
                CP16(bb + sw,        sh + i*16);
                CP16(bb + 8192 + sw, sl + i*16);
            }
            asm volatile("cp.async.commit_group;" ::: "memory");
        }

        // ---- sampling phase: warp samples its 16 px (wid*16..) ----
        int ky = kk/3, kx = kk - ky*3;
#pragma unroll 1
        for (int g = 0; g < 4; g++) {
            int pxl = g*4 + pxg;
            int px = wid*16 + pxl;
            const float* fp = fs + px*28;
            float dy = fp[2*kk], dx = fp[2*kk + 1], m = fp[18 + kk];
            float py  = dy + (float)(h - 1 + ky);
            float pxx = dx + (float)(px - 1 + kx);
            float fy = floorf(py), fx = floorf(pxx);
            int y0 = (int)fy, x0 = (int)fx;
            float ay = py - fy, ax = pxx - fx;
            float w00 = (1.f-ay)*(1.f-ax)*m;
            float w01 = (1.f-ay)*ax*m;
            float w10 = ay*(1.f-ax)*m;
            float w11 = ay*ax*m;
            int y1 = y0 + 1, x1 = x0 + 1;
            if (!(((unsigned)y0 < HH) && ((unsigned)x0 < WW))) w00 = 0.f;
            if (!(((unsigned)y0 < HH) && ((unsigned)x1 < WW))) w01 = 0.f;
            if (!(((unsigned)y1 < HH) && ((unsigned)x0 < WW))) w10 = 0.f;
            if (!(((unsigned)y1 < HH) && ((unsigned)x1 < WW))) w11 = 0.f;
            int yc0 = min(max(y0, 0), HH-1);
            int yc1 = min(max(y1, 0), HH-1);
            int xc0 = min(max(x0, 0), WW-1);
            int xc1 = min(max(x1, 0), WW-1);
            const float* b00 = xp + (yc0*WW + xc0)*CIN;
            const float* b01 = xp + (yc0*WW + xc1)*CIN;
            const float* b10 = xp + (yc1*WW + xc0)*CIN;
            const float* b11 = xp + (yc1*WW + xc1)*CIN;
            unsigned long long w00_2 = pack2f(w00, w00);
            unsigned long long w01_2 = pack2f(w01, w01);
            unsigned long long w10_2 = pack2f(w10, w10);
            unsigned long long w11_2 = pack2f(w11, w11);
#pragma unroll
            for (int half = 0; half < 2; half++) {
                int c0 = chunk*4 + half*32;
                ulonglong2 p00 = *(const ulonglong2*)(b00 + c0);
                ulonglong2 p01 = *(const ulonglong2*)(b01 + c0);
                ulonglong2 p10 = *(const ulonglong2*)(b10 + c0);
                ulonglong2 p11 = *(const ulonglong2*)(b11 + c0);
                unsigned long long v0, v1;
                MUL2(v0, w00_2, p00.x);
                FMA2(v0, w01_2, p01.x, v0);
                FMA2(v0, w10_2, p10.x, v0);
                FMA2(v0, w11_2, p11.x, v0);
                MUL2(v1, w00_2, p00.y);
                FMA2(v1, w01_2, p01.y, v1);
                FMA2(v1, w10_2, p10.y, v1);
                FMA2(v1, w11_2, p11.y, v1);
                float f0, f1, f2, f3;
                unpack2f(v0, f0, f1);
                unpack2f(v1, f2, f3);
                uint32_t h0, h1;
                CVTBF2(h0, f1, f0);   // {hi=f1, lo=f0} -> lane order (f0,f1)
                CVTBF2(h1, f3, f2);
                // residuals: f - bf16(f)
                float r0 = f0 - __bfloat162float(__ushort_as_bfloat16((unsigned short)(h0 & 0xFFFF)));
                float r1 = f1 - __bfloat162float(__ushort_as_bfloat16((unsigned short)(h0 >> 16)));
                float r2 = f2 - __bfloat162float(__ushort_as_bfloat16((unsigned short)(h1 & 0xFFFF)));
                float r3 = f3 - __bfloat162float(__ushort_as_bfloat16((unsigned short)(h1 >> 16)));
                uint32_t lo0, lo1;
                CVTBF2(lo0, r1, r0);
                CVTBF2(lo1, r3, r2);
                uint32_t off = SWZ((uint32_t)(px*128 + c0*2));
                *(uint2*)(sm + AS_HI + off) = make_uint2(h0, h1);
                *(uint2*)(sm + AS_LO + off) = make_uint2(lo0, lo1);
            }
        }

        if (kk < 8)
            asm volatile("cp.async.wait_group 1;" ::: "memory");
        else
            asm volatile("cp.async.wait_group 0;" ::: "memory");
        __syncthreads();   // As written by all warps + Bs[buf] visible

        // ---- mma phase: warp tile 32px x 32o ----
        uint32_t bsb = sbase + BS0 + buf*16384;
        uint32_t b_row = (uint32_t)((lane & 7) + ((lane >> 4) << 3)) * 128;
#pragma unroll
        for (int ks = 0; ks < 4; ks++) {
            uint32_t ah[2][4], al[2][4];
#pragma unroll
            for (int m = 0; m < 2; m++) {
                uint32_t a_off = SWZ((uint32_t)(pxbase + m*16 + (lane & 15))*128
                                     + (uint32_t)(ks*16 + (lane>>4)*8)*2);
                ldsm4(ah[m], sbase + AS_HI + a_off);
                ldsm4(al[m], sbase + AS_LO + a_off);
            }
            uint32_t kc = (uint32_t)(ks*16 + ((lane>>3)&1)*8)*2;
#pragma unroll
            for (int nt = 0; nt < 2; nt++) {
                uint32_t bh[4], bl[4];
                uint32_t b_off = SWZ((uint32_t)(obase + nt*16)*128 + b_row + kc);
                ldsm4(bh, bsb + b_off);
                ldsm4(bl, bsb + 8192 + b_off);
#pragma unroll
                for (int m = 0; m < 2; m++) {
                    mma16816(acc[m][nt*2],   ah[m], bh[0], bh[1]);
                    mma16816(acc[m][nt*2+1], ah[m], bh[2], bh[3]);
                    mma16816(acc[m][nt*2],   ah[m], bl[0], bl[1]);
                    mma16816(acc[m][nt*2+1], ah[m], bl[2], bl[3]);
                    mma16816(acc[m][nt*2],   al[m], bh[0], bh[1]);
                    mma16816(acc[m][nt*2+1], al[m], bh[2], bh[3]);
                }
            }
        }
        __syncthreads();   // all reads done before As/Bs buffer reuse
    }

    // epilogue: out[b][o][h][px]
    int r = lane >> 2, cq = (lane & 3)*2;
#pragma unroll
    for (int m = 0; m < 2; m++) {
        int px0 = pxbase + m*16 + r;
#pragma unroll
        for (int j = 0; j < 4; j++) {
            int o0 = obase + j*8 + cq;
            float* p0 = out + ((size_t)(b*COUT + o0)*HH + h)*WW;
            float* p1 = out + ((size_t)(b*COUT + o0 + 1)*HH + h)*WW;
            p0[px0]     = acc[m][j][0];
            p1[px0]     = acc[m][j][1];
            p0[px0 + 8] = acc[m][j][2];
            p1[px0 + 8] = acc[m][j][3];
        }
    }
}

extern "C" void kernel_launch(void* const* d_in, const int* in_sizes, int n_in,
                              void* d_out, int out_size) {
    const float* x    = (const float*)d_in[0];
    const float* woff = (const float*)d_in[1];
    const float* boff = (const float*)d_in[2];
    const float* wdcn = (const float*)d_in[3];
    float* out = (float*)d_out;

    k_transpose<<<dim3(WW/32, CIN/32, BATCH*HH), dim3(32, 8)>>>(x);
    int repack_n = 9*COUT*CIN + 9*32*CIN;
    k_repack<<<(repack_n + 255)/256, 256>>>(wdcn, woff);

    size_t smO = 81920;   // A[2] 64K + B[2] 16K
    cudaFuncSetAttribute(k_offconv2, cudaFuncAttributeMaxDynamicSharedMemorySize, (int)smO);
    k_offconv2<<<dim3(1, HH, BATCH), 256, smO>>>(boff);

    size_t smM = 79872;   // As 32K + Bs[2] 32K + fs 14K
    cudaFuncSetAttribute(k_main, cudaFuncAttributeMaxDynamicSharedMemorySize, (int)smM);
    k_main<<<dim3(1, HH, BATCH), 256, smM>>>(out);
}

// round 10
// speedup vs baseline: 2.8962x; 1.0517x over previous
#include <cuda_runtime.h>
#include <cuda_bf16.h>
#include <math.h>
#include <stdint.h>

#define BATCH 8
#define CIN   64
#define HH    128
#define WW    128
#define COUT  64

// ---------- packed f32x2 helpers ----------
#define FMA2(d, a, b, c) \
    asm("fma.rn.f32x2 %0, %1, %2, %3;" : "=l"(d) : "l"(a), "l"(b), "l"(c))
#define MUL2(d, a, b) \
    asm("mul.rn.f32x2 %0, %1, %2;" : "=l"(d) : "l"(a), "l"(b))
#define CVTBF2(r, hi, lo) \
    asm("cvt.rn.bf16x2.f32 %0, %1, %2;" : "=r"(r) : "f"(hi), "f"(lo))
__device__ __forceinline__ unsigned long long pack2f(float lo, float hi) {
    unsigned long long r;
    asm("mov.b64 %0, {%1, %2};" : "=l"(r) : "r"(__float_as_uint(lo)), "r"(__float_as_uint(hi)));
    return r;
}
__device__ __forceinline__ void unpack2f(unsigned long long v, float& lo, float& hi) {
    unsigned int a, b;
    asm("mov.b64 {%0, %1}, %2;" : "=r"(a), "=r"(b) : "l"(v));
    lo = __uint_as_float(a); hi = __uint_as_float(b);
}

// ---------- mma helpers ----------
__device__ __forceinline__ uint32_t smem_u32(const void* p) {
    uint32_t a;
    asm("{ .reg .u64 t; cvta.to.shared.u64 t, %1; cvt.u32.u64 %0, t; }" : "=r"(a) : "l"(p));
    return a;
}
__device__ __forceinline__ void ldsm4(uint32_t* r, uint32_t addr) {
    asm volatile("ldmatrix.sync.aligned.m8n8.x4.shared.b16 {%0,%1,%2,%3}, [%4];"
        : "=r"(r[0]), "=r"(r[1]), "=r"(r[2]), "=r"(r[3]) : "r"(addr));
}
__device__ __forceinline__ void mma16816(float* c, const uint32_t* a, uint32_t b0, uint32_t b1) {
    asm volatile("mma.sync.aligned.m16n8k16.row.col.f32.bf16.bf16.f32 "
        "{%0,%1,%2,%3}, {%4,%5,%6,%7}, {%8,%9}, {%0,%1,%2,%3};"
        : "+f"(c[0]), "+f"(c[1]), "+f"(c[2]), "+f"(c[3])
        : "r"(a[0]), "r"(a[1]), "r"(a[2]), "r"(a[3]), "r"(b0), "r"(b1));
}
#define SWZ(o) ((o) ^ (((o) >> 3) & 0x70))
#define CP16(dst, src) \
    asm volatile("cp.async.ca.shared.global [%0], [%1], 16;" :: "r"(dst), "l"(src))
#define CP16Z(dst, src, sz) \
    asm volatile("cp.async.ca.shared.global [%0], [%1], 16, %2;" :: "r"(dst), "l"(src), "r"(sz))

// ---------- scratch ----------
__device__ __align__(16) float g_xnhwc[BATCH*HH*WW*CIN];
__device__ __align__(16) float g_field[BATCH*HH*WW*27];
__device__ __align__(16) __nv_bfloat16 g_xbh[BATCH*HH*WW*CIN];
__device__ __align__(16) __nv_bfloat16 g_xbl[BATCH*HH*WW*CIN];
__device__ __align__(16) __nv_bfloat16 g_wbh[9*COUT*CIN];
__device__ __align__(16) __nv_bfloat16 g_wbl[9*COUT*CIN];
__device__ __align__(16) __nv_bfloat16 g_obh[9*32*CIN];
__device__ __align__(16) __nv_bfloat16 g_obl[9*32*CIN];

// ---------------- transpose NCHW -> NHWC (+ bf16 hi/lo copies) ----------------
__global__ void k_transpose(const float* __restrict__ x) {
    __shared__ float tile[32][33];
    int bh = blockIdx.z;
    int b = bh >> 7, h = bh & 127;
    int w0 = blockIdx.x * 32;
    int c0 = blockIdx.y * 32;
    int tx = threadIdx.x, ty = threadIdx.y;
    const float* src = x + ((b*CIN + c0)*HH + h)*WW + w0;
#pragma unroll
    for (int j = 0; j < 4; j++)
        tile[ty + 8*j][tx] = src[(ty + 8*j)*(HH*WW) + tx];
    __syncthreads();
    size_t base = (size_t)((b*HH + h)*WW + w0)*CIN + c0;
#pragma unroll
    for (int j = 0; j < 4; j++) {
        float v = tile[tx][ty + 8*j];
        size_t idx = base + (size_t)(ty + 8*j)*CIN + tx;
        g_xnhwc[idx] = v;
        __nv_bfloat16 hb = __float2bfloat16(v);
        g_xbh[idx] = hb;
        g_xbl[idx] = __float2bfloat16(v - __bfloat162float(hb));
    }
}

// ---------------- repack weights -> bf16 hi/lo ----------------
__global__ void k_repack(const float* __restrict__ wdcn, const float* __restrict__ woff) {
    int i = blockIdx.x*256 + threadIdx.x;
    if (i < 9*COUT*CIN) {
        int c = i & 63;
        int o = (i >> 6) & 63;
        int k = i >> 12;
        float v = wdcn[(o*CIN + c)*9 + k];
        __nv_bfloat16 hb = __float2bfloat16(v);
        g_wbh[i] = hb;
        g_wbl[i] = __float2bfloat16(v - __bfloat162float(hb));
    }
    int j = i - 9*COUT*CIN;
    if (j >= 0 && j < 9*32*CIN) {
        int c = j & 63;
        int o = (j >> 6) & 31;
        int k = j >> 11;
        float v = (o < 27) ? woff[(o*CIN + c)*9 + k] : 0.f;
        __nv_bfloat16 hb = __float2bfloat16(v);
        g_obh[j] = hb;
        g_obl[j] = __float2bfloat16(v - __bfloat162float(hb));
    }
}

// ---------------- offset conv: cp.async double-buffered HMMA (unchanged) ----------------
__device__ __forceinline__ void off_stage(uint32_t sbase, int b, int h, int kk,
                                          int buf, int tid) {
    int ky = kk/3, kx = kk - ky*3;
    int y = h + ky - 1;
    bool yok = (unsigned)y < HH;
    int yc = min(max(y, 0), HH-1);
    {
        const float4* s4h = (const float4*)(g_obh + kk*(32*CIN));
        const float4* s4l = (const float4*)(g_obl + kk*(32*CIN));
        uint32_t d = sbase + 65536 + buf*8192 + SWZ((uint32_t)(tid*16));
        CP16(d,        s4h + tid);
        CP16(d + 4096, s4l + tid);
    }
    const __nv_bfloat16* rowh = g_xbh + ((size_t)(b*HH + yc)*WW)*CIN;
    const __nv_bfloat16* rowl = g_xbl + ((size_t)(b*HH + yc)*WW)*CIN;
#pragma unroll
    for (int r = 0; r < 4; r++) {
        int i = tid + r*256;
        int px = i >> 3, c16 = i & 7;
        int s = px + kx - 1;
        int sz = (yok && (unsigned)s < WW) ? 16 : 0;
        int sc = min(max(s, 0), WW-1);
        uint32_t d = sbase + buf*32768 + SWZ((uint32_t)(px*128 + c16*16));
        CP16Z(d,         rowh + sc*CIN + c16*8, sz);
        CP16Z(d + 16384, rowl + sc*CIN + c16*8, sz);
    }
}

__global__ void __launch_bounds__(256) k_offconv2(const float* __restrict__ boff) {
    extern __shared__ __align__(1024) char sm[];
    uint32_t sbase = smem_u32(sm);
    int b = blockIdx.z, h = blockIdx.y;
    int tid = threadIdx.x, wid = tid >> 5, lane = tid & 31;

    float acc[4][4];
#pragma unroll
    for (int i = 0; i < 4; i++)
#pragma unroll
        for (int j = 0; j < 4; j++) acc[i][j] = 0.f;

    uint32_t a_row = (uint32_t)(lane & 15) * 128;
    uint32_t b_row = (uint32_t)((lane & 7) + ((lane >> 4) << 3)) * 128;

    off_stage(sbase, b, h, 0, 0, tid);
    asm volatile("cp.async.commit_group;" ::: "memory");

#pragma unroll 1
    for (int kk = 0; kk < 9; kk++) {
        if (kk < 8) {
            off_stage(sbase, b, h, kk + 1, (kk + 1) & 1, tid);
            asm volatile("cp.async.commit_group;" ::: "memory");
            asm volatile("cp.async.wait_group 1;" ::: "memory");
        } else {
            asm volatile("cp.async.wait_group 0;" ::: "memory");
        }
        __syncthreads();

        uint32_t asb = sbase + (kk & 1)*32768 + wid*2048;
        uint32_t bsb = sbase + 65536 + (kk & 1)*8192;
#pragma unroll
        for (int ks = 0; ks < 4; ks++) {
            uint32_t ah[4], al[4];
            uint32_t a_off = SWZ(a_row + (uint32_t)(ks*16 + (lane>>4)*8)*2);
            ldsm4(ah, asb + a_off);
            ldsm4(al, asb + 16384 + a_off);
            uint32_t kc = (uint32_t)(ks*16 + ((lane>>3)&1)*8)*2;
#pragma unroll
            for (int ntp = 0; ntp < 2; ntp++) {
                uint32_t bh[4], bl[4];
                uint32_t b_off = SWZ((uint32_t)(ntp*16)*128 + b_row + kc);
                ldsm4(bh, bsb + b_off);
                ldsm4(bl, bsb + 4096 + b_off);
                mma16816(acc[ntp*2],   ah, bh[0], bh[1]);
                mma16816(acc[ntp*2+1], ah, bh[2], bh[3]);
                mma16816(acc[ntp*2],   ah, bl[0], bl[1]);
                mma16816(acc[ntp*2+1], ah, bl[2], bl[3]);
                mma16816(acc[ntp*2],   al, bh[0], bh[1]);
                mma16816(acc[ntp*2+1], al, bh[2], bh[3]);
            }
        }
        __syncthreads();
    }

    int r = lane >> 2, cq = (lane & 3)*2;
    int px0 = wid*16 + r;
    float* frow = g_field + (size_t)((b*HH + h)*WW)*27;
#pragma unroll
    for (int nt = 0; nt < 4; nt++) {
#pragma unroll
        for (int oi = 0; oi < 2; oi++) {
            int o = nt*8 + cq + oi;
            if (o < 27) {
                float bias = boff[o];
                float v0 = acc[nt][oi]     + bias;
                float v1 = acc[nt][2 + oi] + bias;
                if (o >= 18) {
                    v0 = 1.f/(1.f + __expf(-v0));
                    v1 = 1.f/(1.f + __expf(-v1));
                }
                frow[(size_t)px0*27 + o]       = v0;
                frow[(size_t)(px0 + 8)*27 + o] = v1;
            }
        }
    }
}

// ---------------- k_main: pipelined sample(k+1) / mma(k), double-buffered As+Bs ----------
// smem: As[2] @0/32768 (hi +0 16K, lo +16384 16K); Bs[2] @65536 stride 16384
//       (hi +0, lo +8192); fs @98304 (14336). Total 112640.
__global__ void __launch_bounds__(256, 2) k_main(float* __restrict__ out) {
    extern __shared__ __align__(1024) char sm[];
    const int BS0 = 65536, FS0 = 98304;
    float* fs = (float*)(sm + FS0);
    uint32_t sbase = smem_u32(sm);

    int b = blockIdx.z, h = blockIdx.y;
    int tid = threadIdx.x, wid = tid >> 5, lane = tid & 31;

    {   // per-pixel field cache
        const float* f = g_field + ((size_t)(b*HH + h)*WW)*27;
        for (int e = tid; e < 128*27; e += 256) {
            int p = e / 27;
            int o = e - p*27;
            fs[p*28 + o] = f[e];
        }
    }
    {   // stage B(0) -> Bs[0]
        const char* sh = (const char*)(g_wbh);
        const char* sl = (const char*)(g_wbl);
#pragma unroll
        for (int r = 0; r < 2; r++) {
            int i = tid + r*256;
            uint32_t sw = SWZ((uint32_t)(i*16));
            CP16(sbase + BS0 + sw,        sh + i*16);
            CP16(sbase + BS0 + 8192 + sw, sl + i*16);
        }
        asm volatile("cp.async.commit_group;" ::: "memory");
    }
    __syncthreads();   // fs visible before any sampling read

    const float* xp = g_xnhwc + (size_t)b*(HH*WW*CIN);
    int pxg = lane >> 3, chunk = lane & 7;
    int pxbase = (wid & 3)*32, obase = (wid >> 2)*32;

    // sampler for (tap kk2, group s) -> As buffer at byte offset abuf
    auto sample_g = [&](int kk2, int s, int abuf) {
        int ky = kk2/3, kx = kk2 - ky*3;
        int pxl = s*4 + pxg;
        int px = wid*16 + pxl;
        const float* fp = fs + px*28;
        float dy = fp[2*kk2], dx = fp[2*kk2 + 1], m = fp[18 + kk2];
        float py  = dy + (float)(h - 1 + ky);
        float pxx = dx + (float)(px - 1 + kx);
        float fy = floorf(py), fx = floorf(pxx);
        int y0 = (int)fy, x0 = (int)fx;
        float ay = py - fy, ax = pxx - fx;
        float w00 = (1.f-ay)*(1.f-ax)*m;
        float w01 = (1.f-ay)*ax*m;
        float w10 = ay*(1.f-ax)*m;
        float w11 = ay*ax*m;
        int y1 = y0 + 1, x1 = x0 + 1;
        if (!(((unsigned)y0 < HH) && ((unsigned)x0 < WW))) w00 = 0.f;
        if (!(((unsigned)y0 < HH) && ((unsigned)x1 < WW))) w01 = 0.f;
        if (!(((unsigned)y1 < HH) && ((unsigned)x0 < WW))) w10 = 0.f;
        if (!(((unsigned)y1 < HH) && ((unsigned)x1 < WW))) w11 = 0.f;
        int yc0 = min(max(y0, 0), HH-1);
        int yc1 = min(max(y1, 0), HH-1);
        int xc0 = min(max(x0, 0), WW-1);
        int xc1 = min(max(x1, 0), WW-1);
        const float* b00 = xp + (yc0*WW + xc0)*CIN;
        const float* b01 = xp + (yc0*WW + xc1)*CIN;
        const float* b10 = xp + (yc1*WW + xc0)*CIN;
        const float* b11 = xp + (yc1*WW + xc1)*CIN;
        unsigned long long w00_2 = pack2f(w00, w00);
        unsigned long long w01_2 = pack2f(w01, w01);
        unsigned long long w10_2 = pack2f(w10, w10);
        unsigned long long w11_2 = pack2f(w11, w11);
#pragma unroll
        for (int half = 0; half < 2; half++) {
            int c0 = chunk*4 + half*32;
            ulonglong2 p00 = *(const ulonglong2*)(b00 + c0);
            ulonglong2 p01 = *(const ulonglong2*)(b01 + c0);
            ulonglong2 p10 = *(const ulonglong2*)(b10 + c0);
            ulonglong2 p11 = *(const ulonglong2*)(b11 + c0);
            unsigned long long v0, v1;
            MUL2(v0, w00_2, p00.x);
            FMA2(v0, w01_2, p01.x, v0);
            FMA2(v0, w10_2, p10.x, v0);
            FMA2(v0, w11_2, p11.x, v0);
            MUL2(v1, w00_2, p00.y);
            FMA2(v1, w01_2, p01.y, v1);
            FMA2(v1, w10_2, p10.y, v1);
            FMA2(v1, w11_2, p11.y, v1);
            float f0, f1, f2, f3;
            unpack2f(v0, f0, f1);
            unpack2f(v1, f2, f3);
            uint32_t h0, h1;
            CVTBF2(h0, f1, f0);
            CVTBF2(h1, f3, f2);
            float r0 = f0 - __bfloat162float(__ushort_as_bfloat16((unsigned short)(h0 & 0xFFFF)));
            float r1 = f1 - __bfloat162float(__ushort_as_bfloat16((unsigned short)(h0 >> 16)));
            float r2 = f2 - __bfloat162float(__ushort_as_bfloat16((unsigned short)(h1 & 0xFFFF)));
            float r3 = f3 - __bfloat162float(__ushort_as_bfloat16((unsigned short)(h1 >> 16)));
            uint32_t lo0, lo1;
            CVTBF2(lo0, r1, r0);
            CVTBF2(lo1, r3, r2);
            uint32_t off = SWZ((uint32_t)(px*128 + c0*2));
            *(uint2*)(sm + abuf + off)         = make_uint2(h0, h1);
            *(uint2*)(sm + abuf + 16384 + off) = make_uint2(lo0, lo1);
        }
    };

    // prologue: sample tap 0 -> As[0]
#pragma unroll 1
    for (int s = 0; s < 4; s++) sample_g(0, s, 0);
    asm volatile("cp.async.wait_group 0;" ::: "memory");   // B(0) landed
    __syncthreads();                                        // As[0] visible

    float acc[2][4][4];
#pragma unroll
    for (int m = 0; m < 2; m++)
#pragma unroll
        for (int j = 0; j < 4; j++)
#pragma unroll
            for (int q = 0; q < 4; q++) acc[m][j][q] = 0.f;

#pragma unroll 1
    for (int kk = 0; kk < 9; kk++) {
        int buf = kk & 1;
        bool more = (kk < 8);
        if (more) {   // prefetch B(kk+1) -> Bs[buf^1] (that buffer's reads ended last phase)
            const char* sh = (const char*)(g_wbh + (kk+1)*(COUT*CIN));
            const char* sl = (const char*)(g_wbl + (kk+1)*(COUT*CIN));
            uint32_t bb = sbase + BS0 + (buf^1)*16384;
#pragma unroll
            for (int r = 0; r < 2; r++) {
                int i = tid + r*256;
                uint32_t sw = SWZ((uint32_t)(i*16));
                CP16(bb + sw,        sh + i*16);
                CP16(bb + 8192 + sw, sl + i*16);
            }
            asm volatile("cp.async.commit_group;" ::: "memory");
        }

        uint32_t asb = sbase + buf*32768;
        uint32_t bsb = sbase + BS0 + buf*16384;
        int adst = (buf^1)*32768;
        uint32_t b_row = (uint32_t)((lane & 7) + ((lane >> 4) << 3)) * 128;

        // interleaved: mma step s (tap kk) then sample group s (tap kk+1)
#pragma unroll
        for (int s = 0; s < 4; s++) {
            {   // mma ks = s
                uint32_t ah[2][4], al[2][4];
#pragma unroll
                for (int m = 0; m < 2; m++) {
                    uint32_t a_off = SWZ((uint32_t)(pxbase + m*16 + (lane & 15))*128
                                         + (uint32_t)(s*16 + (lane>>4)*8)*2);
                    ldsm4(ah[m], asb + a_off);
                    ldsm4(al[m], asb + 16384 + a_off);
                }
                uint32_t kc = (uint32_t)(s*16 + ((lane>>3)&1)*8)*2;
#pragma unroll
                for (int nt = 0; nt < 2; nt++) {
                    uint32_t bh[4], bl[4];
                    uint32_t b_off = SWZ((uint32_t)(obase + nt*16)*128 + b_row + kc);
                    ldsm4(bh, bsb + b_off);
                    ldsm4(bl, bsb + 8192 + b_off);
#pragma unroll
                    for (int m = 0; m < 2; m++) {
                        mma16816(acc[m][nt*2],   ah[m], bh[0], bh[1]);
                        mma16816(acc[m][nt*2+1], ah[m], bh[2], bh[3]);
                        mma16816(acc[m][nt*2],   ah[m], bl[0], bl[1]);
                        mma16816(acc[m][nt*2+1], ah[m], bl[2], bl[3]);
                        mma16816(acc[m][nt*2],   al[m], bh[0], bh[1]);
                        mma16816(acc[m][nt*2+1], al[m], bh[2], bh[3]);
                    }
                }
            }
            if (more) sample_g(kk + 1, s, adst);   // overlaps with tensor drain
        }

        if (more) asm volatile("cp.async.wait_group 0;" ::: "memory");
        __syncthreads();   // As[buf^1]+Bs[buf^1] ready; As[buf]/Bs[buf] reads done
    }

    // epilogue: out[b][o][h][px]
    int r = lane >> 2, cq = (lane & 3)*2;
#pragma unroll
    for (int m = 0; m < 2; m++) {
        int px0 = pxbase + m*16 + r;
#pragma unroll
        for (int j = 0; j < 4; j++) {
            int o0 = obase + j*8 + cq;
            float* p0 = out + ((size_t)(b*COUT + o0)*HH + h)*WW;
            float* p1 = out + ((size_t)(b*COUT + o0 + 1)*HH + h)*WW;
            p0[px0]     = acc[m][j][0];
            p1[px0]     = acc[m][j][1];
            p0[px0 + 8] = acc[m][j][2];
            p1[px0 + 8] = acc[m][j][3];
        }
    }
}

extern "C" void kernel_launch(void* const* d_in, const int* in_sizes, int n_in,
                              void* d_out, int out_size) {
    const float* x    = (const float*)d_in[0];
    const float* woff = (const float*)d_in[1];
    const float* boff = (const float*)d_in[2];
    const float* wdcn = (const float*)d_in[3];
    float* out = (float*)d_out;

    k_transpose<<<dim3(WW/32, CIN/32, BATCH*HH), dim3(32, 8)>>>(x);
    int repack_n = 9*COUT*CIN + 9*32*CIN;
    k_repack<<<(repack_n + 255)/256, 256>>>(wdcn, woff);

    size_t smO = 81920;
    cudaFuncSetAttribute(k_offconv2, cudaFuncAttributeMaxDynamicSharedMemorySize, (int)smO);
    k_offconv2<<<dim3(1, HH, BATCH), 256, smO>>>(boff);

    size_t smM = 112640;  // As[2] 64K + Bs[2] 32K + fs 14K
    cudaFuncSetAttribute(k_main, cudaFuncAttributeMaxDynamicSharedMemorySize, (int)smM);
    k_main<<<dim3(1, HH, BATCH), 256, smM>>>(out);
}

// round 11
// speedup vs baseline: 3.1574x; 1.0902x over previous
#include <cuda_runtime.h>
#include <cuda_bf16.h>
#include <math.h>
#include <stdint.h>

#define BATCH 8
#define CIN   64
#define HH    128
#define WW    128
#define COUT  64

// ---------- packed f32x2 helpers ----------
#define FMA2(d, a, b, c) \
    asm("fma.rn.f32x2 %0, %1, %2, %3;" : "=l"(d) : "l"(a), "l"(b), "l"(c))
#define MUL2(d, a, b) \
    asm("mul.rn.f32x2 %0, %1, %2;" : "=l"(d) : "l"(a), "l"(b))
#define CVTBF2(r, hi, lo) \
    asm("cvt.rn.bf16x2.f32 %0, %1, %2;" : "=r"(r) : "f"(hi), "f"(lo))
__device__ __forceinline__ unsigned long long pack2f(float lo, float hi) {
    unsigned long long r;
    asm("mov.b64 %0, {%1, %2};" : "=l"(r) : "r"(__float_as_uint(lo)), "r"(__float_as_uint(hi)));
    return r;
}
__device__ __forceinline__ void unpack2f(unsigned long long v, float& lo, float& hi) {
    unsigned int a, b;
    asm("mov.b64 {%0, %1}, %2;" : "=r"(a), "=r"(b) : "l"(v));
    lo = __uint_as_float(a); hi = __uint_as_float(b);
}

// ---------- mma helpers ----------
__device__ __forceinline__ uint32_t smem_u32(const void* p) {
    uint32_t a;
    asm("{ .reg .u64 t; cvta.to.shared.u64 t, %1; cvt.u32.u64 %0, t; }" : "=r"(a) : "l"(p));
    return a;
}
__device__ __forceinline__ void ldsm4(uint32_t* r, uint32_t addr) {
    asm volatile("ldmatrix.sync.aligned.m8n8.x4.shared.b16 {%0,%1,%2,%3}, [%4];"
        : "=r"(r[0]), "=r"(r[1]), "=r"(r[2]), "=r"(r[3]) : "r"(addr));
}
__device__ __forceinline__ void mma16816(float* c, const uint32_t* a, uint32_t b0, uint32_t b1) {
    asm volatile("mma.sync.aligned.m16n8k16.row.col.f32.bf16.bf16.f32 "
        "{%0,%1,%2,%3}, {%4,%5,%6,%7}, {%8,%9}, {%0,%1,%2,%3};"
        : "+f"(c[0]), "+f"(c[1]), "+f"(c[2]), "+f"(c[3])
        : "r"(a[0]), "r"(a[1]), "r"(a[2]), "r"(a[3]), "r"(b0), "r"(b1));
}
#define SWZ(o) ((o) ^ (((o) >> 3) & 0x70))
#define CP16(dst, src) \
    asm volatile("cp.async.ca.shared.global [%0], [%1], 16;" :: "r"(dst), "l"(src))
#define CP16Z(dst, src, sz) \
    asm volatile("cp.async.ca.shared.global [%0], [%1], 16, %2;" :: "r"(dst), "l"(src), "r"(sz))

// ---------- scratch ----------
__device__ __align__(16) float g_xnhwc[BATCH*HH*WW*CIN];
__device__ __align__(16) __nv_bfloat16 g_xbh[BATCH*HH*WW*CIN];
__device__ __align__(16) __nv_bfloat16 g_xbl[BATCH*HH*WW*CIN];
__device__ __align__(16) __nv_bfloat16 g_wbh[9*COUT*CIN];
__device__ __align__(16) __nv_bfloat16 g_wbl[9*COUT*CIN];
__device__ __align__(16) __nv_bfloat16 g_obh[9*32*CIN];
__device__ __align__(16) __nv_bfloat16 g_obl[9*32*CIN];

// ---------------- transpose NCHW -> NHWC (+ bf16 hi/lo copies) ----------------
__global__ void k_transpose(const float* __restrict__ x) {
    __shared__ float tile[32][33];
    int bh = blockIdx.z;
    int b = bh >> 7, h = bh & 127;
    int w0 = blockIdx.x * 32;
    int c0 = blockIdx.y * 32;
    int tx = threadIdx.x, ty = threadIdx.y;
    const float* src = x + ((b*CIN + c0)*HH + h)*WW + w0;
#pragma unroll
    for (int j = 0; j < 4; j++)
        tile[ty + 8*j][tx] = src[(ty + 8*j)*(HH*WW) + tx];
    __syncthreads();
    size_t base = (size_t)((b*HH + h)*WW + w0)*CIN + c0;
#pragma unroll
    for (int j = 0; j < 4; j++) {
        float v = tile[tx][ty + 8*j];
        size_t idx = base + (size_t)(ty + 8*j)*CIN + tx;
        g_xnhwc[idx] = v;
        __nv_bfloat16 hb = __float2bfloat16(v);
        g_xbh[idx] = hb;
        g_xbl[idx] = __float2bfloat16(v - __bfloat162float(hb));
    }
}

// ---------------- repack weights -> bf16 hi/lo ----------------
__global__ void k_repack(const float* __restrict__ wdcn, const float* __restrict__ woff) {
    int i = blockIdx.x*256 + threadIdx.x;
    if (i < 9*COUT*CIN) {
        int c = i & 63;
        int o = (i >> 6) & 63;
        int k = i >> 12;
        float v = wdcn[(o*CIN + c)*9 + k];
        __nv_bfloat16 hb = __float2bfloat16(v);
        g_wbh[i] = hb;
        g_wbl[i] = __float2bfloat16(v - __bfloat162float(hb));
    }
    int j = i - 9*COUT*CIN;
    if (j >= 0 && j < 9*32*CIN) {
        int c = j & 63;
        int o = (j >> 6) & 31;
        int k = j >> 11;
        float v = (o < 27) ? woff[(o*CIN + c)*9 + k] : 0.f;
        __nv_bfloat16 hb = __float2bfloat16(v);
        g_obh[j] = hb;
        g_obl[j] = __float2bfloat16(v - __bfloat162float(hb));
    }
}

// ---------------- fused: offconv (phase 1) + sample/mma (phase 2) ----------------
// smem layout (112640 B total, 2 CTA/SM):
//   As[2] @0, stride 32768 (hi +0 16K, lo +16384 16K)   -- shared by both phases
//   Bs[2] @65536, stride 16384 (offc: hi +0 4K, lo +4096; main: hi +0 8K, lo +8192)
//   fs    @98304 (128*28*4 = 14336)
#define AS0 0
#define BS0 65536
#define FS0 98304

// stage offconv tap kk: A window (bf16 hi/lo, shifted row) + B slice
__device__ __forceinline__ void off_stage(uint32_t sbase, int b, int h, int kk,
                                          int buf, int tid) {
    int ky = kk/3, kx = kk - ky*3;
    int y = h + ky - 1;
    bool yok = (unsigned)y < HH;
    int yc = min(max(y, 0), HH-1);
    {
        const float4* s4h = (const float4*)(g_obh + kk*(32*CIN));
        const float4* s4l = (const float4*)(g_obl + kk*(32*CIN));
        uint32_t d = sbase + BS0 + buf*16384 + SWZ((uint32_t)(tid*16));
        CP16(d,        s4h + tid);
        CP16(d + 4096, s4l + tid);
    }
    const __nv_bfloat16* rowh = g_xbh + ((size_t)(b*HH + yc)*WW)*CIN;
    const __nv_bfloat16* rowl = g_xbl + ((size_t)(b*HH + yc)*WW)*CIN;
#pragma unroll
    for (int r = 0; r < 4; r++) {
        int i = tid + r*256;
        int px = i >> 3, c16 = i & 7;
        int s = px + kx - 1;
        int sz = (yok && (unsigned)s < WW) ? 16 : 0;
        int sc = min(max(s, 0), WW-1);
        uint32_t d = sbase + AS0 + buf*32768 + SWZ((uint32_t)(px*128 + c16*16));
        CP16Z(d,         rowh + sc*CIN + c16*8, sz);
        CP16Z(d + 16384, rowl + sc*CIN + c16*8, sz);
    }
}

__global__ void __launch_bounds__(256, 2) k_fused(const float* __restrict__ boff,
                                                  float* __restrict__ out) {
    extern __shared__ __align__(1024) char sm[];
    float* fs = (float*)(sm + FS0);
    uint32_t sbase = smem_u32(sm);

    int b = blockIdx.z, h = blockIdx.y;
    int tid = threadIdx.x, wid = tid >> 5, lane = tid & 31;

    // ================= phase 1: offset conv -> fs =================
    {
        float acc[4][4];
#pragma unroll
        for (int i = 0; i < 4; i++)
#pragma unroll
            for (int j = 0; j < 4; j++) acc[i][j] = 0.f;

        uint32_t a_row = (uint32_t)(lane & 15) * 128;
        uint32_t b_row = (uint32_t)((lane & 7) + ((lane >> 4) << 3)) * 128;

        off_stage(sbase, b, h, 0, 0, tid);
        asm volatile("cp.async.commit_group;" ::: "memory");

#pragma unroll 1
        for (int kk = 0; kk < 9; kk++) {
            if (kk < 8) {
                off_stage(sbase, b, h, kk + 1, (kk + 1) & 1, tid);
                asm volatile("cp.async.commit_group;" ::: "memory");
                asm volatile("cp.async.wait_group 1;" ::: "memory");
            } else {
                asm volatile("cp.async.wait_group 0;" ::: "memory");
            }
            __syncthreads();

            uint32_t asb = sbase + AS0 + (kk & 1)*32768 + wid*2048;
            uint32_t bsb = sbase + BS0 + (kk & 1)*16384;
#pragma unroll
            for (int ks = 0; ks < 4; ks++) {
                uint32_t ah[4], al[4];
                uint32_t a_off = SWZ(a_row + (uint32_t)(ks*16 + (lane>>4)*8)*2);
                ldsm4(ah, asb + a_off);
                ldsm4(al, asb + 16384 + a_off);
                uint32_t kc = (uint32_t)(ks*16 + ((lane>>3)&1)*8)*2;
#pragma unroll
                for (int ntp = 0; ntp < 2; ntp++) {
                    uint32_t bh[4], bl[4];
                    uint32_t b_off = SWZ((uint32_t)(ntp*16)*128 + b_row + kc);
                    ldsm4(bh, bsb + b_off);
                    ldsm4(bl, bsb + 4096 + b_off);
                    mma16816(acc[ntp*2],   ah, bh[0], bh[1]);
                    mma16816(acc[ntp*2+1], ah, bh[2], bh[3]);
                    mma16816(acc[ntp*2],   ah, bl[0], bl[1]);
                    mma16816(acc[ntp*2+1], ah, bl[2], bl[3]);
                    mma16816(acc[ntp*2],   al, bh[0], bh[1]);
                    mma16816(acc[ntp*2+1], al, bh[2], bh[3]);
                }
            }
            __syncthreads();
        }

        // epilogue: bias + sigmoid(mask) -> fs[px][o] (stride 28)
        int r = lane >> 2, cq = (lane & 3)*2;
        int px0 = wid*16 + r;
#pragma unroll
        for (int nt = 0; nt < 4; nt++) {
#pragma unroll
            for (int oi = 0; oi < 2; oi++) {
                int o = nt*8 + cq + oi;
                if (o < 27) {
                    float bias = boff[o];
                    float v0 = acc[nt][oi]     + bias;
                    float v1 = acc[nt][2 + oi] + bias;
                    if (o >= 18) {
                        v0 = 1.f/(1.f + __expf(-v0));
                        v1 = 1.f/(1.f + __expf(-v1));
                    }
                    fs[px0*28 + o]       = v0;
                    fs[(px0 + 8)*28 + o] = v1;
                }
            }
        }
    }

    // stage main B(0) -> Bs[0] (hi +0, lo +8192)
    {
        const char* sh = (const char*)(g_wbh);
        const char* sl = (const char*)(g_wbl);
#pragma unroll
        for (int r = 0; r < 2; r++) {
            int i = tid + r*256;
            uint32_t sw = SWZ((uint32_t)(i*16));
            CP16(sbase + BS0 + sw,        sh + i*16);
            CP16(sbase + BS0 + 8192 + sw, sl + i*16);
        }
        asm volatile("cp.async.commit_group;" ::: "memory");
    }
    __syncthreads();   // fs visible to all warps; offconv buffers free

    // ================= phase 2: sample + mma =================
    const float* xp = g_xnhwc + (size_t)b*(HH*WW*CIN);
    int pxg = lane >> 3, chunk = lane & 7;
    int pxbase = (wid & 3)*32, obase = (wid >> 2)*32;

    auto sample_g = [&](int kk2, int s, int abuf) {
        int ky = kk2/3, kx = kk2 - ky*3;
        int pxl = s*4 + pxg;
        int px = wid*16 + pxl;
        const float* fp = fs + px*28;
        float dy = fp[2*kk2], dx = fp[2*kk2 + 1], m = fp[18 + kk2];
        float py  = dy + (float)(h - 1 + ky);
        float pxx = dx + (float)(px - 1 + kx);
        float fy = floorf(py), fx = floorf(pxx);
        int y0 = (int)fy, x0 = (int)fx;
        float ay = py - fy, ax = pxx - fx;
        float w00 = (1.f-ay)*(1.f-ax)*m;
        float w01 = (1.f-ay)*ax*m;
        float w10 = ay*(1.f-ax)*m;
        float w11 = ay*ax*m;
        int y1 = y0 + 1, x1 = x0 + 1;
        if (!(((unsigned)y0 < HH) && ((unsigned)x0 < WW))) w00 = 0.f;
        if (!(((unsigned)y0 < HH) && ((unsigned)x1 < WW))) w01 = 0.f;
        if (!(((unsigned)y1 < HH) && ((unsigned)x0 < WW))) w10 = 0.f;
        if (!(((unsigned)y1 < HH) && ((unsigned)x1 < WW))) w11 = 0.f;
        int yc0 = min(max(y0, 0), HH-1);
        int yc1 = min(max(y1, 0), HH-1);
        int xc0 = min(max(x0, 0), WW-1);
        int xc1 = min(max(x1, 0), WW-1);
        const float* b00 = xp + (yc0*WW + xc0)*CIN;
        const float* b01 = xp + (yc0*WW + xc1)*CIN;
        const float* b10 = xp + (yc1*WW + xc0)*CIN;
        const float* b11 = xp + (yc1*WW + xc1)*CIN;
        unsigned long long w00_2 = pack2f(w00, w00);
        unsigned long long w01_2 = pack2f(w01, w01);
        unsigned long long w10_2 = pack2f(w10, w10);
        unsigned long long w11_2 = pack2f(w11, w11);
#pragma unroll
        for (int half = 0; half < 2; half++) {
            int c0 = chunk*4 + half*32;
            ulonglong2 p00 = *(const ulonglong2*)(b00 + c0);
            ulonglong2 p01 = *(const ulonglong2*)(b01 + c0);
            ulonglong2 p10 = *(const ulonglong2*)(b10 + c0);
            ulonglong2 p11 = *(const ulonglong2*)(b11 + c0);
            unsigned long long v0, v1;
            MUL2(v0, w00_2, p00.x);
            FMA2(v0, w01_2, p01.x, v0);
            FMA2(v0, w10_2, p10.x, v0);
            FMA2(v0, w11_2, p11.x, v0);
            MUL2(v1, w00_2, p00.y);
            FMA2(v1, w01_2, p01.y, v1);
            FMA2(v1, w10_2, p10.y, v1);
            FMA2(v1, w11_2, p11.y, v1);
            float f0, f1, f2, f3;
            unpack2f(v0, f0, f1);
            unpack2f(v1, f2, f3);
            uint32_t h0, h1;
            CVTBF2(h0, f1, f0);
            CVTBF2(h1, f3, f2);
            float r0 = f0 - __bfloat162float(__ushort_as_bfloat16((unsigned short)(h0 & 0xFFFF)));
            float r1 = f1 - __bfloat162float(__ushort_as_bfloat16((unsigned short)(h0 >> 16)));
            float r2 = f2 - __bfloat162float(__ushort_as_bfloat16((unsigned short)(h1 & 0xFFFF)));
            float r3 = f3 - __bfloat162float(__ushort_as_bfloat16((unsigned short)(h1 >> 16)));
            uint32_t lo0, lo1;
            CVTBF2(lo0, r1, r0);
            CVTBF2(lo1, r3, r2);
            uint32_t off = SWZ((uint32_t)(px*128 + c0*2));
            *(uint2*)(sm + abuf + off)         = make_uint2(h0, h1);
            *(uint2*)(sm + abuf + 16384 + off) = make_uint2(lo0, lo1);
        }
    };

    // prologue: sample tap 0 -> As[0] (B(0) cp.async drains underneath)
#pragma unroll 1
    for (int s = 0; s < 4; s++) sample_g(0, s, AS0);
    asm volatile("cp.async.wait_group 0;" ::: "memory");
    __syncthreads();

    float acc[2][4][4];
#pragma unroll
    for (int m = 0; m < 2; m++)
#pragma unroll
        for (int j = 0; j < 4; j++)
#pragma unroll
            for (int q = 0; q < 4; q++) acc[m][j][q] = 0.f;

#pragma unroll 1
    for (int kk = 0; kk < 9; kk++) {
        int buf = kk & 1;
        bool more = (kk < 8);
        if (more) {   // prefetch B(kk+1) -> Bs[buf^1]
            const char* sh = (const char*)(g_wbh + (kk+1)*(COUT*CIN));
            const char* sl = (const char*)(g_wbl + (kk+1)*(COUT*CIN));
            uint32_t bb = sbase + BS0 + (buf^1)*16384;
#pragma unroll
            for (int r = 0; r < 2; r++) {
                int i = tid + r*256;
                uint32_t sw = SWZ((uint32_t)(i*16));
                CP16(bb + sw,        sh + i*16);
                CP16(bb + 8192 + sw, sl + i*16);
            }
            asm volatile("cp.async.commit_group;" ::: "memory");
        }

        uint32_t asb = sbase + AS0 + buf*32768;
        uint32_t bsb = sbase + BS0 + buf*16384;
        int adst = AS0 + (buf^1)*32768;
        uint32_t b_row = (uint32_t)((lane & 7) + ((lane >> 4) << 3)) * 128;

#pragma unroll
        for (int s = 0; s < 4; s++) {
            {   // mma ks = s (tap kk)
                uint32_t ah[2][4], al[2][4];
#pragma unroll
                for (int m = 0; m < 2; m++) {
                    uint32_t a_off = SWZ((uint32_t)(pxbase + m*16 + (lane & 15))*128
                                         + (uint32_t)(s*16 + (lane>>4)*8)*2);
                    ldsm4(ah[m], asb + a_off);
                    ldsm4(al[m], asb + 16384 + a_off);
                }
                uint32_t kc = (uint32_t)(s*16 + ((lane>>3)&1)*8)*2;
#pragma unroll
                for (int nt = 0; nt < 2; nt++) {
                    uint32_t bh[4], bl[4];
                    uint32_t b_off = SWZ((uint32_t)(obase + nt*16)*128 + b_row + kc);
                    ldsm4(bh, bsb + b_off);
                    ldsm4(bl, bsb + 8192 + b_off);
#pragma unroll
                    for (int m = 0; m < 2; m++) {
                        mma16816(acc[m][nt*2],   ah[m], bh[0], bh[1]);
                        mma16816(acc[m][nt*2+1], ah[m], bh[2], bh[3]);
                        mma16816(acc[m][nt*2],   ah[m], bl[0], bl[1]);
                        mma16816(acc[m][nt*2+1], ah[m], bl[2], bl[3]);
                        mma16816(acc[m][nt*2],   al[m], bh[0], bh[1]);
                        mma16816(acc[m][nt*2+1], al[m], bh[2], bh[3]);
                    }
                }
            }
            if (more) sample_g(kk + 1, s, adst);   // overlap with tensor drain
        }

        if (more) asm volatile("cp.async.wait_group 0;" ::: "memory");
        __syncthreads();
    }

    // epilogue: out[b][o][h][px]
    int r = lane >> 2, cq = (lane & 3)*2;
#pragma unroll
    for (int m = 0; m < 2; m++) {
        int px0 = pxbase + m*16 + r;
#pragma unroll
        for (int j = 0; j < 4; j++) {
            int o0 = obase + j*8 + cq;
            float* p0 = out + ((size_t)(b*COUT + o0)*HH + h)*WW;
            float* p1 = out + ((size_t)(b*COUT + o0 + 1)*HH + h)*WW;
            p0[px0]     = acc[m][j][0];
            p1[px0]     = acc[m][j][1];
            p0[px0 + 8] = acc[m][j][2];
            p1[px0 + 8] = acc[m][j][3];
        }
    }
}

extern "C" void kernel_launch(void* const* d_in, const int* in_sizes, int n_in,
                              void* d_out, int out_size) {
    const float* x    = (const float*)d_in[0];
    const float* woff = (const float*)d_in[1];
    const float* boff = (const float*)d_in[2];
    const float* wdcn = (const float*)d_in[3];
    float* out = (float*)d_out;

    k_transpose<<<dim3(WW/32, CIN/32, BATCH*HH), dim3(32, 8)>>>(x);
    int repack_n = 9*COUT*CIN + 9*32*CIN;
    k_repack<<<(repack_n + 255)/256, 256>>>(wdcn, woff);

    size_t smF = 112640;  // As[2] 64K + Bs[2] 32K + fs 14K
    cudaFuncSetAttribute(k_fused, cudaFuncAttributeMaxDynamicSharedMemorySize, (int)smF);
    k_fused<<<dim3(1, HH, BATCH), 256, smF>>>(boff, out);
}

// round 12
// speedup vs baseline: 5.7178x; 1.8109x over previous
#include <cuda_runtime.h>
#include <cuda_fp16.h>
#include <math.h>
#include <stdint.h>

#define BATCH 8
#define CIN   64
#define HH    128
#define WW    128
#define COUT  64

// ---------- fp16x2 helpers ----------
#define HMUL2(d, a, b) \
    asm("mul.rn.f16x2 %0, %1, %2;" : "=r"(d) : "r"(a), "r"(b))
#define HFMA2(d, a, b, c) \
    asm("fma.rn.f16x2 %0, %1, %2, %3;" : "=r"(d) : "r"(a), "r"(b), "r"(c))
#define CVTH2(r, f) \
    asm("cvt.rn.f16x2.f32 %0, %1, %2;" : "=r"(r) : "f"(f), "f"(f))

// ---------- mma helpers ----------
__device__ __forceinline__ uint32_t smem_u32(const void* p) {
    uint32_t a;
    asm("{ .reg .u64 t; cvta.to.shared.u64 t, %1; cvt.u32.u64 %0, t; }" : "=r"(a) : "l"(p));
    return a;
}
__device__ __forceinline__ void ldsm4(uint32_t* r, uint32_t addr) {
    asm volatile("ldmatrix.sync.aligned.m8n8.x4.shared.b16 {%0,%1,%2,%3}, [%4];"
        : "=r"(r[0]), "=r"(r[1]), "=r"(r[2]), "=r"(r[3]) : "r"(addr));
}
__device__ __forceinline__ void mma16816(float* c, const uint32_t* a, uint32_t b0, uint32_t b1) {
    asm volatile("mma.sync.aligned.m16n8k16.row.col.f32.f16.f16.f32 "
        "{%0,%1,%2,%3}, {%4,%5,%6,%7}, {%8,%9}, {%0,%1,%2,%3};"
        : "+f"(c[0]), "+f"(c[1]), "+f"(c[2]), "+f"(c[3])
        : "r"(a[0]), "r"(a[1]), "r"(a[2]), "r"(a[3]), "r"(b0), "r"(b1));
}
#define SWZ(o) ((o) ^ (((o) >> 3) & 0x70))
#define CP16(dst, src) \
    asm volatile("cp.async.ca.shared.global [%0], [%1], 16;" :: "r"(dst), "l"(src))
#define CP16Z(dst, src, sz) \
    asm volatile("cp.async.ca.shared.global [%0], [%1], 16, %2;" :: "r"(dst), "l"(src), "r"(sz))

// ---------- scratch ----------
__device__ __align__(16) __half g_xfh[BATCH*HH*WW*CIN];   // NHWC fp16 x
__device__ __align__(16) __half g_wfh[9*COUT*CIN];        // dcn [k][o][c] fp16
__device__ __align__(16) __half g_ofh[9*32*CIN];          // off [k][o(pad32)][c] fp16

// ---------------- transpose NCHW -> NHWC fp16 ----------------
__global__ void k_transpose(const float* __restrict__ x) {
    __shared__ float tile[32][33];
    int bh = blockIdx.z;
    int b = bh >> 7, h = bh & 127;
    int w0 = blockIdx.x * 32;
    int c0 = blockIdx.y * 32;
    int tx = threadIdx.x, ty = threadIdx.y;
    const float* src = x + ((b*CIN + c0)*HH + h)*WW + w0;
#pragma unroll
    for (int j = 0; j < 4; j++)
        tile[ty + 8*j][tx] = src[(ty + 8*j)*(HH*WW) + tx];   // tile[c_local][w_local]
    __syncthreads();
    int t = ty*32 + tx;
    int cp = t & 15;            // c-pair index
    int wl0 = t >> 4;           // 0..15
    size_t rowbase = (size_t)((b*HH + h)*WW + w0)*CIN + c0;
#pragma unroll
    for (int jw = 0; jw < 2; jw++) {
        int wl = wl0 + 16*jw;
        float v0 = tile[2*cp][wl];
        float v1 = tile[2*cp + 1][wl];
        __half2 hv = __floats2half2_rn(v0, v1);
        *(__half2*)(g_xfh + rowbase + (size_t)wl*CIN + 2*cp) = hv;
    }
}

// ---------------- repack weights -> fp16 ----------------
__global__ void k_repack(const float* __restrict__ wdcn, const float* __restrict__ woff) {
    int i = blockIdx.x*256 + threadIdx.x;
    if (i < 9*COUT*CIN) {
        int c = i & 63;
        int o = (i >> 6) & 63;
        int k = i >> 12;
        g_wfh[i] = __float2half(wdcn[(o*CIN + c)*9 + k]);
    }
    int j = i - 9*COUT*CIN;
    if (j >= 0 && j < 9*32*CIN) {
        int c = j & 63;
        int o = (j >> 6) & 31;
        int k = j >> 11;
        g_ofh[j] = __float2half((o < 27) ? woff[(o*CIN + c)*9 + k] : 0.f);
    }
}

// ---------------- fused kernel ----------------
// smem: As[2] @0, stride 16384 (128px x 128B fp16, SW128)
//       Bs[2] @32768, stride 8192 (phase1: 4KB; phase2: 8KB)
//       fs    @49152 (128*28*4 = 14336).  Total 63488. 2 CTA/SM.
#define AS0 0
#define BS0 32768
#define FS0 49152

__device__ __forceinline__ void off_stage(uint32_t sbase, int b, int h, int kk,
                                          int buf, int tid) {
    int ky = kk/3, kx = kk - ky*3;
    int y = h + ky - 1;
    bool yok = (unsigned)y < HH;
    int yc = min(max(y, 0), HH-1);
    {   // B slice: 32o x 64c fp16 = 4KB
        const float4* s4 = (const float4*)(g_ofh + kk*(32*CIN));
        uint32_t d = sbase + BS0 + buf*8192 + SWZ((uint32_t)(tid*16));
        CP16(d, s4 + tid);
    }
    const __half* row = g_xfh + ((size_t)(b*HH + yc)*WW)*CIN;
#pragma unroll
    for (int r = 0; r < 4; r++) {
        int i = tid + r*256;
        int px = i >> 3, c16 = i & 7;
        int s = px + kx - 1;
        int sz = (yok && (unsigned)s < WW) ? 16 : 0;
        int sc = min(max(s, 0), WW-1);
        uint32_t d = sbase + AS0 + buf*16384 + SWZ((uint32_t)(px*128 + c16*16));
        CP16Z(d, row + sc*CIN + c16*8, sz);
    }
}

__global__ void __launch_bounds__(256, 2) k_fused(const float* __restrict__ boff,
                                                  float* __restrict__ out) {
    extern __shared__ __align__(1024) char sm[];
    float* fs = (float*)(sm + FS0);
    uint32_t sbase = smem_u32(sm);

    int b = blockIdx.z, h = blockIdx.y;
    int tid = threadIdx.x, wid = tid >> 5, lane = tid & 31;

    // ================= phase 1: offset conv -> fs =================
    {
        float acc[2][2][4];   // warp tile 32px x 16o
#pragma unroll
        for (int m = 0; m < 2; m++)
#pragma unroll
            for (int j = 0; j < 2; j++)
#pragma unroll
                for (int q = 0; q < 4; q++) acc[m][j][q] = 0.f;

        int pxbase1 = (wid & 3)*32, obase1 = (wid >> 2)*16;
        uint32_t b_row = (uint32_t)((lane & 7) + ((lane >> 4) << 3)) * 128;

        off_stage(sbase, b, h, 0, 0, tid);
        asm volatile("cp.async.commit_group;" ::: "memory");

#pragma unroll 1
        for (int kk = 0; kk < 9; kk++) {
            if (kk < 8) {
                off_stage(sbase, b, h, kk + 1, (kk + 1) & 1, tid);
                asm volatile("cp.async.commit_group;" ::: "memory");
                asm volatile("cp.async.wait_group 1;" ::: "memory");
            } else {
                asm volatile("cp.async.wait_group 0;" ::: "memory");
            }
            __syncthreads();

            uint32_t asb = sbase + AS0 + (kk & 1)*16384;
            uint32_t bsb = sbase + BS0 + (kk & 1)*8192;
#pragma unroll
            for (int ks = 0; ks < 4; ks++) {
                uint32_t ah[2][4];
#pragma unroll
                for (int m = 0; m < 2; m++) {
                    uint32_t a_off = SWZ((uint32_t)(pxbase1 + m*16 + (lane & 15))*128
                                         + (uint32_t)(ks*16 + (lane>>4)*8)*2);
                    ldsm4(ah[m], asb + a_off);
                }
                uint32_t kc = (uint32_t)(ks*16 + ((lane>>3)&1)*8)*2;
                uint32_t bb[4];
                uint32_t b_off = SWZ((uint32_t)obase1*128 + b_row + kc);
                ldsm4(bb, bsb + b_off);
#pragma unroll
                for (int m = 0; m < 2; m++) {
                    mma16816(acc[m][0], ah[m], bb[0], bb[1]);
                    mma16816(acc[m][1], ah[m], bb[2], bb[3]);
                }
            }
            __syncthreads();
        }

        // epilogue: bias + sigmoid(mask) -> fs
        int r = lane >> 2, cq = (lane & 3)*2;
#pragma unroll
        for (int m = 0; m < 2; m++) {
            int px0 = pxbase1 + m*16 + r;
#pragma unroll
            for (int j = 0; j < 2; j++) {
#pragma unroll
                for (int oi = 0; oi < 2; oi++) {
                    int o = obase1 + j*8 + cq + oi;
                    if (o < 27) {
                        float bias = boff[o];
                        float v0 = acc[m][j][oi]     + bias;
                        float v1 = acc[m][j][2 + oi] + bias;
                        if (o >= 18) {
                            v0 = 1.f/(1.f + __expf(-v0));
                            v1 = 1.f/(1.f + __expf(-v1));
                        }
                        fs[px0*28 + o]       = v0;
                        fs[(px0 + 8)*28 + o] = v1;
                    }
                }
            }
        }
    }

    // stage main B(0) -> Bs[0] (8KB)
    {
        const float4* s4 = (const float4*)(g_wfh);
#pragma unroll
        for (int r = 0; r < 2; r++) {
            int i = tid + r*256;
            uint32_t sw = SWZ((uint32_t)(i*16));
            CP16(sbase + BS0 + sw, s4 + i);
        }
        asm volatile("cp.async.commit_group;" ::: "memory");
    }
    __syncthreads();   // fs visible; phase-1 buffers free

    // ================= phase 2: sample + mma =================
    const __half* xp = g_xfh + (size_t)b*(HH*WW*CIN);
    int pxg = lane >> 3, chunk = lane & 7;
    int pxbase = (wid & 3)*32, obase = (wid >> 2)*32;

    auto sample_g = [&](int kk2, int s, int abuf) {
        int ky = kk2/3, kx = kk2 - ky*3;
        int pxl = s*4 + pxg;
        int px = wid*16 + pxl;
        const float* fp = fs + px*28;
        float dy = fp[2*kk2], dx = fp[2*kk2 + 1], m = fp[18 + kk2];
        float py  = dy + (float)(h - 1 + ky);
        float pxx = dx + (float)(px - 1 + kx);
        float fy = floorf(py), fx = floorf(pxx);
        int y0 = (int)fy, x0 = (int)fx;
        float ay = py - fy, ax = pxx - fx;
        float w00 = (1.f-ay)*(1.f-ax)*m;
        float w01 = (1.f-ay)*ax*m;
        float w10 = ay*(1.f-ax)*m;
        float w11 = ay*ax*m;
        int y1 = y0 + 1, x1 = x0 + 1;
        if (!(((unsigned)y0 < HH) && ((unsigned)x0 < WW))) w00 = 0.f;
        if (!(((unsigned)y0 < HH) && ((unsigned)x1 < WW))) w01 = 0.f;
        if (!(((unsigned)y1 < HH) && ((unsigned)x0 < WW))) w10 = 0.f;
        if (!(((unsigned)y1 < HH) && ((unsigned)x1 < WW))) w11 = 0.f;
        int yc0 = min(max(y0, 0), HH-1);
        int yc1 = min(max(y1, 0), HH-1);
        int xc0 = min(max(x0, 0), WW-1);
        int xc1 = min(max(x1, 0), WW-1);
        uint32_t w00h, w01h, w10h, w11h;
        CVTH2(w00h, w00);
        CVTH2(w01h, w01);
        CVTH2(w10h, w10);
        CVTH2(w11h, w11);
        uint4 p00 = *(const uint4*)(xp + (yc0*WW + xc0)*CIN + chunk*8);
        uint4 p01 = *(const uint4*)(xp + (yc0*WW + xc1)*CIN + chunk*8);
        uint4 p10 = *(const uint4*)(xp + (yc1*WW + xc0)*CIN + chunk*8);
        uint4 p11 = *(const uint4*)(xp + (yc1*WW + xc1)*CIN + chunk*8);
        uint4 v;
        HMUL2(v.x, w00h, p00.x); HFMA2(v.x, w01h, p01.x, v.x);
        HFMA2(v.x, w10h, p10.x, v.x); HFMA2(v.x, w11h, p11.x, v.x);
        HMUL2(v.y, w00h, p00.y); HFMA2(v.y, w01h, p01.y, v.y);
        HFMA2(v.y, w10h, p10.y, v.y); HFMA2(v.y, w11h, p11.y, v.y);
        HMUL2(v.z, w00h, p00.z); HFMA2(v.z, w01h, p01.z, v.z);
        HFMA2(v.z, w10h, p10.z, v.z); HFMA2(v.z, w11h, p11.z, v.z);
        HMUL2(v.w, w00h, p00.w); HFMA2(v.w, w01h, p01.w, v.w);
        HFMA2(v.w, w10h, p10.w, v.w); HFMA2(v.w, w11h, p11.w, v.w);
        *(uint4*)(sm + abuf + SWZ((uint32_t)(px*128 + chunk*16))) = v;
    };

    // prologue: sample tap 0 -> As[0]
#pragma unroll 1
    for (int s = 0; s < 4; s++) sample_g(0, s, AS0);
    asm volatile("cp.async.wait_group 0;" ::: "memory");
    __syncthreads();

    float acc[2][4][4];
#pragma unroll
    for (int m = 0; m < 2; m++)
#pragma unroll
        for (int j = 0; j < 4; j++)
#pragma unroll
            for (int q = 0; q < 4; q++) acc[m][j][q] = 0.f;

#pragma unroll 1
    for (int kk = 0; kk < 9; kk++) {
        int buf = kk & 1;
        bool more = (kk < 8);
        if (more) {   // prefetch B(kk+1) -> Bs[buf^1]
            const float4* s4 = (const float4*)(g_wfh + (kk+1)*(COUT*CIN));
            uint32_t bb = sbase + BS0 + (buf^1)*8192;
#pragma unroll
            for (int r = 0; r < 2; r++) {
                int i = tid + r*256;
                CP16(bb + SWZ((uint32_t)(i*16)), s4 + i);
            }
            asm volatile("cp.async.commit_group;" ::: "memory");
        }

        uint32_t asb = sbase + AS0 + buf*16384;
        uint32_t bsb = sbase + BS0 + buf*8192;
        int adst = AS0 + (buf^1)*16384;
        uint32_t b_row = (uint32_t)((lane & 7) + ((lane >> 4) << 3)) * 128;

#pragma unroll
        for (int s = 0; s < 4; s++) {
            {   // mma ks = s (tap kk)
                uint32_t ah[2][4];
#pragma unroll
                for (int m = 0; m < 2; m++) {
                    uint32_t a_off = SWZ((uint32_t)(pxbase + m*16 + (lane & 15))*128
                                         + (uint32_t)(s*16 + (lane>>4)*8)*2);
                    ldsm4(ah[m], asb + a_off);
                }
                uint32_t kc = (uint32_t)(s*16 + ((lane>>3)&1)*8)*2;
#pragma unroll
                for (int nt = 0; nt < 2; nt++) {
                    uint32_t bb[4];
                    uint32_t b_off = SWZ((uint32_t)(obase + nt*16)*128 + b_row + kc);
                    ldsm4(bb, bsb + b_off);
#pragma unroll
                    for (int m = 0; m < 2; m++) {
                        mma16816(acc[m][nt*2],   ah[m], bb[0], bb[1]);
                        mma16816(acc[m][nt*2+1], ah[m], bb[2], bb[3]);
                    }
                }
            }
            if (more) sample_g(kk + 1, s, adst);   // overlap with tensor drain
        }

        if (more) asm volatile("cp.async.wait_group 0;" ::: "memory");
        __syncthreads();
    }

    // epilogue: out[b][o][h][px]
    int r = lane >> 2, cq = (lane & 3)*2;
#pragma unroll
    for (int m = 0; m < 2; m++) {
        int px0 = pxbase + m*16 + r;
#pragma unroll
        for (int j = 0; j < 4; j++) {
            int o0 = obase + j*8 + cq;
            float* p0 = out + ((size_t)(b*COUT + o0)*HH + h)*WW;
            float* p1 = out + ((size_t)(b*COUT + o0 + 1)*HH + h)*WW;
            p0[px0]     = acc[m][j][0];
            p1[px0]     = acc[m][j][1];
            p0[px0 + 8] = acc[m][j][2];
            p1[px0 + 8] = acc[m][j][3];
        }
    }
}

extern "C" void kernel_launch(void* const* d_in, const int* in_sizes, int n_in,
                              void* d_out, int out_size) {
    const float* x    = (const float*)d_in[0];
    const float* woff = (const float*)d_in[1];
    const float* boff = (const float*)d_in[2];
    const float* wdcn = (const float*)d_in[3];
    float* out = (float*)d_out;

    k_transpose<<<dim3(WW/32, CIN/32, BATCH*HH), dim3(32, 8)>>>(x);
    int repack_n = 9*COUT*CIN + 9*32*CIN;
    k_repack<<<(repack_n + 255)/256, 256>>>(wdcn, woff);

    size_t smF = 63488;   // As[2] 32K + Bs[2] 16K + fs 14K
    cudaFuncSetAttribute(k_fused, cudaFuncAttributeMaxDynamicSharedMemorySize, (int)smF);
    k_fused<<<dim3(1, HH, BATCH), 256, smF>>>(boff, out);
}

// round 13
// speedup vs baseline: 5.8194x; 1.0178x over previous
#include <cuda_runtime.h>
#include <cuda_fp16.h>
#include <math.h>
#include <stdint.h>

#define BATCH 8
#define CIN   64
#define HH    128
#define WW    128
#define COUT  64

// ---------- fp16x2 helpers ----------
#define HMUL2(d, a, b) \
    asm("mul.rn.f16x2 %0, %1, %2;" : "=r"(d) : "r"(a), "r"(b))
#define HFMA2(d, a, b, c) \
    asm("fma.rn.f16x2 %0, %1, %2, %3;" : "=r"(d) : "r"(a), "r"(b), "r"(c))
#define CVTH2(r, f) \
    asm("cvt.rn.f16x2.f32 %0, %1, %2;" : "=r"(r) : "f"(f), "f"(f))

// ---------- mma helpers ----------
__device__ __forceinline__ uint32_t smem_u32(const void* p) {
    uint32_t a;
    asm("{ .reg .u64 t; cvta.to.shared.u64 t, %1; cvt.u32.u64 %0, t; }" : "=r"(a) : "l"(p));
    return a;
}
__device__ __forceinline__ void ldsm4(uint32_t* r, uint32_t addr) {
    asm volatile("ldmatrix.sync.aligned.m8n8.x4.shared.b16 {%0,%1,%2,%3}, [%4];"
        : "=r"(r[0]), "=r"(r[1]), "=r"(r[2]), "=r"(r[3]) : "r"(addr));
}
__device__ __forceinline__ void mma16816(float* c, const uint32_t* a, uint32_t b0, uint32_t b1) {
    asm volatile("mma.sync.aligned.m16n8k16.row.col.f32.f16.f16.f32 "
        "{%0,%1,%2,%3}, {%4,%5,%6,%7}, {%8,%9}, {%0,%1,%2,%3};"
        : "+f"(c[0]), "+f"(c[1]), "+f"(c[2]), "+f"(c[3])
        : "r"(a[0]), "r"(a[1]), "r"(a[2]), "r"(a[3]), "r"(b0), "r"(b1));
}
#define SWZ(o) ((o) ^ (((o) >> 3) & 0x70))
#define CP16(dst, src) \
    asm volatile("cp.async.ca.shared.global [%0], [%1], 16;" :: "r"(dst), "l"(src))
#define CP16Z(dst, src, sz) \
    asm volatile("cp.async.ca.shared.global [%0], [%1], 16, %2;" :: "r"(dst), "l"(src), "r"(sz))

// ---------- scratch ----------
__device__ __align__(16) __half g_xfh[BATCH*HH*WW*CIN];   // NHWC fp16 x
__device__ __align__(16) __half g_wfh[9*COUT*CIN];        // dcn [k][o][c] fp16
__device__ __align__(16) __half g_ofh[9*32*CIN];          // off [k][o(pad32)][c] fp16

// ---------------- transpose NCHW -> NHWC fp16 ----------------
__global__ void k_transpose(const float* __restrict__ x) {
    __shared__ float tile[32][33];
    int bh = blockIdx.z;
    int b = bh >> 7, h = bh & 127;
    int w0 = blockIdx.x * 32;
    int c0 = blockIdx.y * 32;
    int tx = threadIdx.x, ty = threadIdx.y;
    const float* src = x + ((b*CIN + c0)*HH + h)*WW + w0;
#pragma unroll
    for (int j = 0; j < 4; j++)
        tile[ty + 8*j][tx] = src[(ty + 8*j)*(HH*WW) + tx];
    __syncthreads();
    int t = ty*32 + tx;
    int cp = t & 15;
    int wl0 = t >> 4;
    size_t rowbase = (size_t)((b*HH + h)*WW + w0)*CIN + c0;
#pragma unroll
    for (int jw = 0; jw < 2; jw++) {
        int wl = wl0 + 16*jw;
        float v0 = tile[2*cp][wl];
        float v1 = tile[2*cp + 1][wl];
        __half2 hv = __floats2half2_rn(v0, v1);
        *(__half2*)(g_xfh + rowbase + (size_t)wl*CIN + 2*cp) = hv;
    }
}

// ---------------- repack weights -> fp16 ----------------
__global__ void k_repack(const float* __restrict__ wdcn, const float* __restrict__ woff) {
    int i = blockIdx.x*256 + threadIdx.x;
    if (i < 9*COUT*CIN) {
        int c = i & 63;
        int o = (i >> 6) & 63;
        int k = i >> 12;
        g_wfh[i] = __float2half(wdcn[(o*CIN + c)*9 + k]);
    }
    int j = i - 9*COUT*CIN;
    if (j >= 0 && j < 9*32*CIN) {
        int c = j & 63;
        int o = (j >> 6) & 31;
        int k = j >> 11;
        g_ofh[j] = __float2half((o < 27) ? woff[(o*CIN + c)*9 + k] : 0.f);
    }
}

// ---------------- fused kernel ----------------
// phase-1 smem: RB[3] @0, stride 17408 (130 slots x 128B, zero-padded ends)
//               OBS @52224 (9 x 4096 offconv B slices) -> 89088
// phase-2 smem (written only after phase-1 completes):
//               As[2] @0 stride 16384; Bs[2] @32768 stride 8192; fs @49152 (14336)
// Total 89088. 2 CTA/SM.
#define RB_STRIDE 17408
#define OBS 52224
#define AS0 0
#define BS0 32768
#define FS0 49152

__global__ void __launch_bounds__(256, 2) k_fused(const float* __restrict__ boff,
                                                  float* __restrict__ out) {
    extern __shared__ __align__(1024) char sm[];
    float* fs = (float*)(sm + FS0);
    uint32_t sbase = smem_u32(sm);

    int b = blockIdx.z, h = blockIdx.y;
    int tid = threadIdx.x, wid = tid >> 5, lane = tid & 31;

    // ================= phase 1: offset conv -> fs =================
    {
        // zero pad slots 0 and 129 of each row buffer
        if (tid < 48) {
            int rrow = tid >> 4;
            int slot = (tid >> 3) & 1;
            int c16 = tid & 7;
            uint32_t po = (slot ? 129u*128u : 0u) + (uint32_t)c16*16;
            *(uint4*)(sm + rrow*RB_STRIDE + SWZ(po)) = make_uint4(0,0,0,0);
        }
        // stage 3 input rows (full 128 px, slot = px+1)
#pragma unroll
        for (int ky = 0; ky < 3; ky++) {
            int y = h + ky - 1;
            bool yok = (unsigned)y < HH;
            int yc = min(max(y, 0), HH-1);
            const __half* row = g_xfh + ((size_t)(b*HH + yc)*WW)*CIN;
            uint32_t rb = sbase + ky*RB_STRIDE;
            int sz = yok ? 16 : 0;
#pragma unroll
            for (int r = 0; r < 4; r++) {
                int i = tid + r*256;
                int px = i >> 3, c16 = i & 7;
                CP16Z(rb + SWZ((uint32_t)((px + 1)*128 + c16*16)), row + px*CIN + c16*8, sz);
            }
        }
        // stage all 9 offconv B slices
        {
            const float4* s4 = (const float4*)g_ofh;
#pragma unroll
            for (int r = 0; r < 9; r++) {
                int i = tid + r*256;
                uint32_t d = sbase + OBS + (uint32_t)(i >> 8)*4096
                             + SWZ((uint32_t)((i & 255)*16));
                CP16(d, s4 + i);
            }
        }
        asm volatile("cp.async.commit_group;" ::: "memory");
        asm volatile("cp.async.wait_group 0;" ::: "memory");
        __syncthreads();

        float acc[2][2][4];   // warp tile 32px x 16o
#pragma unroll
        for (int m = 0; m < 2; m++)
#pragma unroll
            for (int j = 0; j < 2; j++)
#pragma unroll
                for (int q = 0; q < 4; q++) acc[m][j][q] = 0.f;

        int pxbase1 = (wid & 3)*32, obase1 = (wid >> 2)*16;
        uint32_t b_row = (uint32_t)((lane & 7) + ((lane >> 4) << 3)) * 128;

        // 9 taps, zero barriers: all operands read-only
#pragma unroll 1
        for (int kk = 0; kk < 9; kk++) {
            int ky = kk/3, kx = kk - ky*3;
            uint32_t rb  = sbase + ky*RB_STRIDE;
            uint32_t bbk = sbase + OBS + kk*4096;
#pragma unroll
            for (int ks = 0; ks < 4; ks++) {
                uint32_t ah[2][4];
#pragma unroll
                for (int m = 0; m < 2; m++) {
                    uint32_t a_off = SWZ((uint32_t)(pxbase1 + m*16 + (lane & 15) + kx)*128
                                         + (uint32_t)(ks*16 + (lane>>4)*8)*2);
                    ldsm4(ah[m], rb + a_off);
                }
                uint32_t kc = (uint32_t)(ks*16 + ((lane>>3)&1)*8)*2;
                uint32_t bb[4];
                ldsm4(bb, bbk + SWZ((uint32_t)obase1*128 + b_row + kc));
#pragma unroll
                for (int m = 0; m < 2; m++) {
                    mma16816(acc[m][0], ah[m], bb[0], bb[1]);
                    mma16816(acc[m][1], ah[m], bb[2], bb[3]);
                }
            }
        }
        __syncthreads();   // RB/OBS reads done before fs (aliased) is written

        // epilogue: bias + sigmoid(mask) -> fs
        int r = lane >> 2, cq = (lane & 3)*2;
#pragma unroll
        for (int m = 0; m < 2; m++) {
            int px0 = pxbase1 + m*16 + r;
#pragma unroll
            for (int j = 0; j < 2; j++) {
#pragma unroll
                for (int oi = 0; oi < 2; oi++) {
                    int o = obase1 + j*8 + cq + oi;
                    if (o < 27) {
                        float bias = boff[o];
                        float v0 = acc[m][j][oi]     + bias;
                        float v1 = acc[m][j][2 + oi] + bias;
                        if (o >= 18) {
                            v0 = 1.f/(1.f + __expf(-v0));
                            v1 = 1.f/(1.f + __expf(-v1));
                        }
                        fs[px0*28 + o]       = v0;
                        fs[(px0 + 8)*28 + o] = v1;
                    }
                }
            }
        }
    }

    // stage main B(0) -> Bs[0]
    {
        const float4* s4 = (const float4*)(g_wfh);
#pragma unroll
        for (int r = 0; r < 2; r++) {
            int i = tid + r*256;
            CP16(sbase + BS0 + SWZ((uint32_t)(i*16)), s4 + i);
        }
        asm volatile("cp.async.commit_group;" ::: "memory");
    }
    __syncthreads();   // fs visible; phase-1 buffers free

    // ================= phase 2: sample + mma =================
    const __half* xp = g_xfh + (size_t)b*(HH*WW*CIN);
    int pxg = lane >> 3, chunk = lane & 7;
    int pxbase = (wid & 3)*32, obase = (wid >> 2)*32;

    auto sample_g = [&](int kk2, int s, int abuf) {
        int ky = kk2/3, kx = kk2 - ky*3;
        int pxl = s*4 + pxg;
        int px = wid*16 + pxl;
        const float* fp = fs + px*28;
        float dy = fp[2*kk2], dx = fp[2*kk2 + 1], m = fp[18 + kk2];
        float py  = dy + (float)(h - 1 + ky);
        float pxx = dx + (float)(px - 1 + kx);
        float fy = floorf(py), fx = floorf(pxx);
        int y0 = (int)fy, x0 = (int)fx;
        float ay = py - fy, ax = pxx - fx;
        float w00 = (1.f-ay)*(1.f-ax)*m;
        float w01 = (1.f-ay)*ax*m;
        float w10 = ay*(1.f-ax)*m;
        float w11 = ay*ax*m;
        int y1 = y0 + 1, x1 = x0 + 1;
        if (!(((unsigned)y0 < HH) && ((unsigned)x0 < WW))) w00 = 0.f;
        if (!(((unsigned)y0 < HH) && ((unsigned)x1 < WW))) w01 = 0.f;
        if (!(((unsigned)y1 < HH) && ((unsigned)x0 < WW))) w10 = 0.f;
        if (!(((unsigned)y1 < HH) && ((unsigned)x1 < WW))) w11 = 0.f;
        int yc0 = min(max(y0, 0), HH-1);
        int yc1 = min(max(y1, 0), HH-1);
        int xc0 = min(max(x0, 0), WW-1);
        int xc1 = min(max(x1, 0), WW-1);
        uint32_t w00h, w01h, w10h, w11h;
        CVTH2(w00h, w00);
        CVTH2(w01h, w01);
        CVTH2(w10h, w10);
        CVTH2(w11h, w11);
        uint4 p00 = *(const uint4*)(xp + (yc0*WW + xc0)*CIN + chunk*8);
        uint4 p01 = *(const uint4*)(xp + (yc0*WW + xc1)*CIN + chunk*8);
        uint4 p10 = *(const uint4*)(xp + (yc1*WW + xc0)*CIN + chunk*8);
        uint4 p11 = *(const uint4*)(xp + (yc1*WW + xc1)*CIN + chunk*8);
        uint4 v;
        HMUL2(v.x, w00h, p00.x); HFMA2(v.x, w01h, p01.x, v.x);
        HFMA2(v.x, w10h, p10.x, v.x); HFMA2(v.x, w11h, p11.x, v.x);
        HMUL2(v.y, w00h, p00.y); HFMA2(v.y, w01h, p01.y, v.y);
        HFMA2(v.y, w10h, p10.y, v.y); HFMA2(v.y, w11h, p11.y, v.y);
        HMUL2(v.z, w00h, p00.z); HFMA2(v.z, w01h, p01.z, v.z);
        HFMA2(v.z, w10h, p10.z, v.z); HFMA2(v.z, w11h, p11.z, v.z);
        HMUL2(v.w, w00h, p00.w); HFMA2(v.w, w01h, p01.w, v.w);
        HFMA2(v.w, w10h, p10.w, v.w); HFMA2(v.w, w11h, p11.w, v.w);
        *(uint4*)(sm + abuf + SWZ((uint32_t)(px*128 + chunk*16))) = v;
    };

    // prologue: sample tap 0 -> As[0]
#pragma unroll 1
    for (int s = 0; s < 4; s++) sample_g(0, s, AS0);
    asm volatile("cp.async.wait_group 0;" ::: "memory");
    __syncthreads();

    float acc[2][4][4];
#pragma unroll
    for (int m = 0; m < 2; m++)
#pragma unroll
        for (int j = 0; j < 4; j++)
#pragma unroll
            for (int q = 0; q < 4; q++) acc[m][j][q] = 0.f;

#pragma unroll 1
    for (int kk = 0; kk < 9; kk++) {
        int buf = kk & 1;
        bool more = (kk < 8);
        if (more) {   // prefetch B(kk+1) -> Bs[buf^1]
            const float4* s4 = (const float4*)(g_wfh + (kk+1)*(COUT*CIN));
            uint32_t bb = sbase + BS0 + (buf^1)*8192;
#pragma unroll
            for (int r = 0; r < 2; r++) {
                int i = tid + r*256;
                CP16(bb + SWZ((uint32_t)(i*16)), s4 + i);
            }
            asm volatile("cp.async.commit_group;" ::: "memory");
        }

        uint32_t asb = sbase + AS0 + buf*16384;
        uint32_t bsb = sbase + BS0 + buf*8192;
        int adst = AS0 + (buf^1)*16384;
        uint32_t b_row = (uint32_t)((lane & 7) + ((lane >> 4) << 3)) * 128;

#pragma unroll
        for (int s = 0; s < 4; s++) {
            {   // mma ks = s (tap kk)
                uint32_t ah[2][4];
#pragma unroll
                for (int m = 0; m < 2; m++) {
                    uint32_t a_off = SWZ((uint32_t)(pxbase + m*16 + (lane & 15))*128
                                         + (uint32_t)(s*16 + (lane>>4)*8)*2);
                    ldsm4(ah[m], asb + a_off);
                }
                uint32_t kc = (uint32_t)(s*16 + ((lane>>3)&1)*8)*2;
#pragma unroll
                for (int nt = 0; nt < 2; nt++) {
                    uint32_t bb[4];
                    uint32_t b_off = SWZ((uint32_t)(obase + nt*16)*128 + b_row + kc);
                    ldsm4(bb, bsb + b_off);
#pragma unroll
                    for (int m = 0; m < 2; m++) {
                        mma16816(acc[m][nt*2],   ah[m], bb[0], bb[1]);
                        mma16816(acc[m][nt*2+1], ah[m], bb[2], bb[3]);
                    }
                }
            }
            if (more) sample_g(kk + 1, s, adst);   // overlap with tensor drain
        }

        if (more) asm volatile("cp.async.wait_group 0;" ::: "memory");
        __syncthreads();
    }

    // epilogue: out[b][o][h][px]
    int r = lane >> 2, cq = (lane & 3)*2;
#pragma unroll
    for (int m = 0; m < 2; m++) {
        int px0 = pxbase + m*16 + r;
#pragma unroll
        for (int j = 0; j < 4; j++) {
            int o0 = obase + j*8 + cq;
            float* p0 = out + ((size_t)(b*COUT + o0)*HH + h)*WW;
            float* p1 = out + ((size_t)(b*COUT + o0 + 1)*HH + h)*WW;
            p0[px0]     = acc[m][j][0];
            p1[px0]     = acc[m][j][1];
            p0[px0 + 8] = acc[m][j][2];
            p1[px0 + 8] = acc[m][j][3];
        }
    }
}

extern "C" void kernel_launch(void* const* d_in, const int* in_sizes, int n_in,
                              void* d_out, int out_size) {
    const float* x    = (const float*)d_in[0];
    const float* woff = (const float*)d_in[1];
    const float* boff = (const float*)d_in[2];
    const float* wdcn = (const float*)d_in[3];
    float* out = (float*)d_out;

    k_transpose<<<dim3(WW/32, CIN/32, BATCH*HH), dim3(32, 8)>>>(x);
    int repack_n = 9*COUT*CIN + 9*32*CIN;
    k_repack<<<(repack_n + 255)/256, 256>>>(wdcn, woff);

    size_t smF = 89088;   // max(RB+OBS, As[2]+Bs[2]+fs)
    cudaFuncSetAttribute(k_fused, cudaFuncAttributeMaxDynamicSharedMemorySize, (int)smF);
    k_fused<<<dim3(1, HH, BATCH), 256, smF>>>(boff, out);
}

// round 14
// speedup vs baseline: 5.8326x; 1.0023x over previous
#include <cuda_runtime.h>
#include <cuda_fp16.h>
#include <math.h>
#include <stdint.h>

#define BATCH 8
#define CIN   64
#define HH    128
#define WW    128
#define COUT  64

// ---------- fp16x2 helpers ----------
#define HMUL2(d, a, b) \
    asm("mul.rn.f16x2 %0, %1, %2;" : "=r"(d) : "r"(a), "r"(b))
#define HFMA2(d, a, b, c) \
    asm("fma.rn.f16x2 %0, %1, %2, %3;" : "=r"(d) : "r"(a), "r"(b), "r"(c))
#define CVTH2(r, f) \
    asm("cvt.rn.f16x2.f32 %0, %1, %2;" : "=r"(r) : "f"(f), "f"(f))

// ---------- mma helpers ----------
__device__ __forceinline__ uint32_t smem_u32(const void* p) {
    uint32_t a;
    asm("{ .reg .u64 t; cvta.to.shared.u64 t, %1; cvt.u32.u64 %0, t; }" : "=r"(a) : "l"(p));
    return a;
}
__device__ __forceinline__ void ldsm4(uint32_t* r, uint32_t addr) {
    asm volatile("ldmatrix.sync.aligned.m8n8.x4.shared.b16 {%0,%1,%2,%3}, [%4];"
        : "=r"(r[0]), "=r"(r[1]), "=r"(r[2]), "=r"(r[3]) : "r"(addr));
}
__device__ __forceinline__ void mma16816(float* c, const uint32_t* a, uint32_t b0, uint32_t b1) {
    asm volatile("mma.sync.aligned.m16n8k16.row.col.f32.f16.f16.f32 "
        "{%0,%1,%2,%3}, {%4,%5,%6,%7}, {%8,%9}, {%0,%1,%2,%3};"
        : "+f"(c[0]), "+f"(c[1]), "+f"(c[2]), "+f"(c[3])
        : "r"(a[0]), "r"(a[1]), "r"(a[2]), "r"(a[3]), "r"(b0), "r"(b1));
}
#define SWZ(o) ((o) ^ (((o) >> 3) & 0x70))
#define CP16(dst, src) \
    asm volatile("cp.async.ca.shared.global [%0], [%1], 16;" :: "r"(dst), "l"(src))
#define CP16Z(dst, src, sz) \
    asm volatile("cp.async.ca.shared.global [%0], [%1], 16, %2;" :: "r"(dst), "l"(src), "r"(sz))
#define BARN(id) \
    asm volatile("bar.sync %0, 64;" :: "r"(id) : "memory")

// ---------- scratch ----------
__device__ __align__(16) __half g_xfh[BATCH*HH*WW*CIN];   // NHWC fp16 x
__device__ __align__(16) __half g_wfh[9*COUT*CIN];        // dcn [k][o][c] fp16
__device__ __align__(16) __half g_ofh[9*32*CIN];          // off [k][o(pad32)][c] fp16

// ---------------- transpose NCHW -> NHWC fp16 (coalesced 128B writes) ----------------
__global__ void __launch_bounds__(256) k_transpose(const float* __restrict__ x) {
    __shared__ float tile[64][33];
    int bh = blockIdx.z;
    int b = bh >> 7, h = bh & 127;
    int w0 = blockIdx.x * 32;
    int tid = threadIdx.x;
    const float* src = x + ((size_t)(b*CIN)*HH + h)*WW + w0;
#pragma unroll
    for (int r = 0; r < 2; r++) {
        int i = tid + r*256;
        int c = i >> 3, wq = i & 7;
        float4 v = *(const float4*)(src + (size_t)c*(HH*WW) + wq*4);
        tile[c][wq*4+0] = v.x;
        tile[c][wq*4+1] = v.y;
        tile[c][wq*4+2] = v.z;
        tile[c][wq*4+3] = v.w;
    }
    __syncthreads();
    int px = tid >> 3, chunk = tid & 7;
    int c0 = chunk*8;
    __half2 h01 = __floats2half2_rn(tile[c0+0][px], tile[c0+1][px]);
    __half2 h23 = __floats2half2_rn(tile[c0+2][px], tile[c0+3][px]);
    __half2 h45 = __floats2half2_rn(tile[c0+4][px], tile[c0+5][px]);
    __half2 h67 = __floats2half2_rn(tile[c0+6][px], tile[c0+7][px]);
    uint4 v = make_uint4(*(uint32_t*)&h01, *(uint32_t*)&h23,
                         *(uint32_t*)&h45, *(uint32_t*)&h67);
    *(uint4*)(g_xfh + ((size_t)(b*HH + h)*WW + w0 + px)*CIN + c0) = v;
}

// ---------------- repack weights -> fp16 ----------------
__global__ void k_repack(const float* __restrict__ wdcn, const float* __restrict__ woff) {
    int i = blockIdx.x*256 + threadIdx.x;
    if (i < 9*COUT*CIN) {
        int c = i & 63;
        int o = (i >> 6) & 63;
        int k = i >> 12;
        g_wfh[i] = __float2half(wdcn[(o*CIN + c)*9 + k]);
    }
    int j = i - 9*COUT*CIN;
    if (j >= 0 && j < 9*32*CIN) {
        int c = j & 63;
        int o = (j >> 6) & 31;
        int k = j >> 11;
        g_ofh[j] = __float2half((o < 27) ? woff[(o*CIN + c)*9 + k] : 0.f);
    }
}

// ---------------- fused kernel ----------------
// phase-1 smem: RB[3] @0 stride 17408 (130x128B rows); OBS @52224 (9x4096) -> 89088
// phase-2 smem: As[2] @0 stride 16384; fs @32768 (14336); BM @47104 (8x8192) -> 112640
#define RB_STRIDE 17408
#define OBS 52224
#define AS0 0
#define FS0 32768
#define BM  47104

__global__ void __launch_bounds__(256, 2) k_fused(const float* __restrict__ boff,
                                                  float* __restrict__ out) {
    extern __shared__ __align__(1024) char sm[];
    float* fs = (float*)(sm + FS0);
    uint32_t sbase = smem_u32(sm);

    int b = blockIdx.z, h = blockIdx.y;
    int tid = threadIdx.x, wid = tid >> 5, lane = tid & 31;

    // ================= phase 1: offset conv =================
    float p1acc[2][2][4];
    {
        if (tid < 48) {
            int rrow = tid >> 4;
            int slot = (tid >> 3) & 1;
            int c16 = tid & 7;
            uint32_t po = (slot ? 129u*128u : 0u) + (uint32_t)c16*16;
            *(uint4*)(sm + rrow*RB_STRIDE + SWZ(po)) = make_uint4(0,0,0,0);
        }
#pragma unroll
        for (int ky = 0; ky < 3; ky++) {
            int y = h + ky - 1;
            bool yok = (unsigned)y < HH;
            int yc = min(max(y, 0), HH-1);
            const __half* row = g_xfh + ((size_t)(b*HH + yc)*WW)*CIN;
            uint32_t rb = sbase + ky*RB_STRIDE;
            int sz = yok ? 16 : 0;
#pragma unroll
            for (int r = 0; r < 4; r++) {
                int i = tid + r*256;
                int px = i >> 3, c16 = i & 7;
                CP16Z(rb + SWZ((uint32_t)((px + 1)*128 + c16*16)), row + px*CIN + c16*8, sz);
            }
        }
        {
            const float4* s4 = (const float4*)g_ofh;
#pragma unroll
            for (int r = 0; r < 9; r++) {
                int i = tid + r*256;
                uint32_t d = sbase + OBS + (uint32_t)(i >> 8)*4096
                             + SWZ((uint32_t)((i & 255)*16));
                CP16(d, s4 + i);
            }
        }
        asm volatile("cp.async.commit_group;" ::: "memory");
        asm volatile("cp.async.wait_group 0;" ::: "memory");
        __syncthreads();

#pragma unroll
        for (int m = 0; m < 2; m++)
#pragma unroll
            for (int j = 0; j < 2; j++)
#pragma unroll
                for (int q = 0; q < 4; q++) p1acc[m][j][q] = 0.f;

        int pxbase1 = (wid & 3)*32, obase1 = (wid >> 2)*16;
        uint32_t b_row = (uint32_t)((lane & 7) + ((lane >> 4) << 3)) * 128;

#pragma unroll 1
        for (int kk = 0; kk < 9; kk++) {
            int ky = kk/3, kx = kk - ky*3;
            uint32_t rb  = sbase + ky*RB_STRIDE;
            uint32_t bbk = sbase + OBS + kk*4096;
#pragma unroll
            for (int ks = 0; ks < 4; ks++) {
                uint32_t ah[2][4];
#pragma unroll
                for (int m = 0; m < 2; m++) {
                    uint32_t a_off = SWZ((uint32_t)(pxbase1 + m*16 + (lane & 15) + kx)*128
                                         + (uint32_t)(ks*16 + (lane>>4)*8)*2);
                    ldsm4(ah[m], rb + a_off);
                }
                uint32_t kc = (uint32_t)(ks*16 + ((lane>>3)&1)*8)*2;
                uint32_t bb[4];
                ldsm4(bb, bbk + SWZ((uint32_t)obase1*128 + b_row + kc));
#pragma unroll
                for (int m = 0; m < 2; m++) {
                    mma16816(p1acc[m][0], ah[m], bb[0], bb[1]);
                    mma16816(p1acc[m][1], ah[m], bb[2], bb[3]);
                }
            }
        }
        __syncthreads();   // RB/OBS reads done; regions reusable

        // epilogue: bias + sigmoid(mask) -> fs
        int r = lane >> 2, cq = (lane & 3)*2;
#pragma unroll
        for (int m = 0; m < 2; m++) {
            int px0 = pxbase1 + m*16 + r;
#pragma unroll
            for (int j = 0; j < 2; j++) {
#pragma unroll
                for (int oi = 0; oi < 2; oi++) {
                    int o = obase1 + j*8 + cq + oi;
                    if (o < 27) {
                        float bias = boff[o];
                        float v0 = p1acc[m][j][oi]     + bias;
                        float v1 = p1acc[m][j][2 + oi] + bias;
                        if (o >= 18) {
                            v0 = 1.f/(1.f + __expf(-v0));
                            v1 = 1.f/(1.f + __expf(-v1));
                        }
                        fs[px0*28 + o]       = v0;
                        fs[(px0 + 8)*28 + o] = v1;
                    }
                }
            }
        }
    }

    // stage main B(0..7) -> BM (64KB, resident)
    {
        const float4* s4 = (const float4*)g_wfh;
#pragma unroll
        for (int r = 0; r < 16; r++) {
            int i = tid + r*256;
            uint32_t d = sbase + BM + (uint32_t)(i >> 9)*8192
                         + SWZ((uint32_t)((i & 511)*16));
            CP16(d, s4 + i);
        }
        asm volatile("cp.async.commit_group;" ::: "memory");
    }
    __syncthreads();   // fs visible to all warps

    // ================= phase 2: sample + mma =================
    const __half* xp = g_xfh + (size_t)b*(HH*WW*CIN);
    int pxg = lane >> 3, chunk = lane & 7;
    int grp = wid & 3;
    int pxbase = grp*32, obase = (wid >> 2)*32;
    int spx_base = grp*32 + (wid >> 2)*16;   // warp's 16 sampled px live in its own group

    auto sample_g = [&](int kk2, int s, int abuf) {
        int ky = kk2/3, kx = kk2 - ky*3;
        int px = spx_base + s*4 + pxg;
        const float* fp = fs + px*28;
        float dy = fp[2*kk2], dx = fp[2*kk2 + 1], m = fp[18 + kk2];
        float py  = dy + (float)(h - 1 + ky);
        float pxx = dx + (float)(px - 1 + kx);
        float fy = floorf(py), fx = floorf(pxx);
        int y0 = (int)fy, x0 = (int)fx;
        float ay = py - fy, ax = pxx - fx;
        float w00 = (1.f-ay)*(1.f-ax)*m;
        float w01 = (1.f-ay)*ax*m;
        float w10 = ay*(1.f-ax)*m;
        float w11 = ay*ax*m;
        int y1 = y0 + 1, x1 = x0 + 1;
        if (!(((unsigned)y0 < HH) && ((unsigned)x0 < WW))) w00 = 0.f;
        if (!(((unsigned)y0 < HH) && ((unsigned)x1 < WW))) w01 = 0.f;
        if (!(((unsigned)y1 < HH) && ((unsigned)x0 < WW))) w10 = 0.f;
        if (!(((unsigned)y1 < HH) && ((unsigned)x1 < WW))) w11 = 0.f;
        int yc0 = min(max(y0, 0), HH-1);
        int yc1 = min(max(y1, 0), HH-1);
        int xc0 = min(max(x0, 0), WW-1);
        int xc1 = min(max(x1, 0), WW-1);
        uint32_t w00h, w01h, w10h, w11h;
        CVTH2(w00h, w00);
        CVTH2(w01h, w01);
        CVTH2(w10h, w10);
        CVTH2(w11h, w11);
        uint4 p00 = *(const uint4*)(xp + (yc0*WW + xc0)*CIN + chunk*8);
        uint4 p01 = *(const uint4*)(xp + (yc0*WW + xc1)*CIN + chunk*8);
        uint4 p10 = *(const uint4*)(xp + (yc1*WW + xc0)*CIN + chunk*8);
        uint4 p11 = *(const uint4*)(xp + (yc1*WW + xc1)*CIN + chunk*8);
        uint4 v;
        HMUL2(v.x, w00h, p00.x); HFMA2(v.x, w01h, p01.x, v.x);
        HFMA2(v.x, w10h, p10.x, v.x); HFMA2(v.x, w11h, p11.x, v.x);
        HMUL2(v.y, w00h, p00.y); HFMA2(v.y, w01h, p01.y, v.y);
        HFMA2(v.y, w10h, p10.y, v.y); HFMA2(v.y, w11h, p11.y, v.y);
        HMUL2(v.z, w00h, p00.z); HFMA2(v.z, w01h, p01.z, v.z);
        HFMA2(v.z, w10h, p10.z, v.z); HFMA2(v.z, w11h, p11.z, v.z);
        HMUL2(v.w, w00h, p00.w); HFMA2(v.w, w01h, p01.w, v.w);
        HFMA2(v.w, w10h, p10.w, v.w); HFMA2(v.w, w11h, p11.w, v.w);
        *(uint4*)(sm + abuf + SWZ((uint32_t)(px*128 + chunk*16))) = v;
    };

    // prologue: sample tap 0 -> As[0]
#pragma unroll 1
    for (int s = 0; s < 4; s++) sample_g(0, s, AS0);
    asm volatile("cp.async.wait_group 0;" ::: "memory");   // BM landed
    __syncthreads();                                        // BM + As[0] visible

    float acc[2][4][4];
#pragma unroll
    for (int m = 0; m < 2; m++)
#pragma unroll
        for (int j = 0; j < 4; j++)
#pragma unroll
            for (int q = 0; q < 4; q++) acc[m][j][q] = 0.f;

    uint32_t b_row = (uint32_t)((lane & 7) + ((lane >> 4) << 3)) * 128;

#pragma unroll 1
    for (int kk = 0; kk < 9; kk++) {
        int buf = kk & 1;
        bool more = (kk < 8);
        if (kk == 1) {   // stage B(8) into BM slot 0 (slot dead after tap-0 block barrier)
            const float4* s8 = (const float4*)(g_wfh + 8*(COUT*CIN));
#pragma unroll
            for (int r = 0; r < 2; r++) {
                int i = tid + r*256;
                CP16(sbase + BM + SWZ((uint32_t)(i*16)), s8 + i);
            }
            asm volatile("cp.async.commit_group;" ::: "memory");
        }

        uint32_t asb = sbase + AS0 + buf*16384;
        uint32_t bsb = sbase + BM + (uint32_t)(kk & 7)*8192;   // kk=8 -> slot 0
        int adst = AS0 + (buf^1)*16384;

#pragma unroll
        for (int s = 0; s < 4; s++) {
            {   // mma ks = s (tap kk)
                uint32_t ah[2][4];
#pragma unroll
                for (int m = 0; m < 2; m++) {
                    uint32_t a_off = SWZ((uint32_t)(pxbase + m*16 + (lane & 15))*128
                                         + (uint32_t)(s*16 + (lane>>4)*8)*2);
                    ldsm4(ah[m], asb + a_off);
                }
                uint32_t kc = (uint32_t)(s*16 + ((lane>>3)&1)*8)*2;
#pragma unroll
                for (int nt = 0; nt < 2; nt++) {
                    uint32_t bb[4];
                    uint32_t b_off = SWZ((uint32_t)(obase + nt*16)*128 + b_row + kc);
                    ldsm4(bb, bsb + b_off);
#pragma unroll
                    for (int m = 0; m < 2; m++) {
                        mma16816(acc[m][nt*2],   ah[m], bb[0], bb[1]);
                        mma16816(acc[m][nt*2+1], ah[m], bb[2], bb[3]);
                    }
                }
            }
            if (more) sample_g(kk + 1, s, adst);
        }

        // barriers: block at taps 0 and 7 (B slot-0 lifecycle); group-local otherwise
        if (kk == 0) {
            __syncthreads();
        } else if (kk == 7) {
            asm volatile("cp.async.wait_group 0;" ::: "memory");   // B(8) landed
            __syncthreads();
        } else if (more) {
            BARN(1 + grp);
        }
    }

    // epilogue: out[b][o][h][px]
    int r = lane >> 2, cq = (lane & 3)*2;
#pragma unroll
    for (int m = 0; m < 2; m++) {
        int px0 = pxbase + m*16 + r;
#pragma unroll
        for (int j = 0; j < 4; j++) {
            int o0 = obase + j*8 + cq;
            float* p0 = out + ((size_t)(b*COUT + o0)*HH + h)*WW;
            float* p1 = out + ((size_t)(b*COUT + o0 + 1)*HH + h)*WW;
            p0[px0]     = acc[m][j][0];
            p1[px0]     = acc[m][j][1];
            p0[px0 + 8] = acc[m][j][2];
            p1[px0 + 8] = acc[m][j][3];
        }
    }
}

extern "C" void kernel_launch(void* const* d_in, const int* in_sizes, int n_in,
                              void* d_out, int out_size) {
    const float* x    = (const float*)d_in[0];
    const float* woff = (const float*)d_in[1];
    const float* boff = (const float*)d_in[2];
    const float* wdcn = (const float*)d_in[3];
    float* out = (float*)d_out;

    k_transpose<<<dim3(WW/32, 1, BATCH*HH), 256>>>(x);
    int repack_n = 9*COUT*CIN + 9*32*CIN;
    k_repack<<<(repack_n + 255)/256, 256>>>(wdcn, woff);

    size_t smF = 112640;   // max(RB+OBS=89088, As[2]+fs+BM=112640)
    cudaFuncSetAttribute(k_fused, cudaFuncAttributeMaxDynamicSharedMemorySize, (int)smF);
    k_fused<<<dim3(1, HH, BATCH), 256, smF>>>(boff, out);
}